// round 7
// baseline (speedup 1.0000x reference)
#include <cuda_runtime.h>
#include <cuda_fp16.h>
#include <math.h>

#define N_OBJ 256
#define C_CLS 151
#define HDIM  512
#define NCROW (N_OBJ * C_CLS)
#define KX    1536
#define CH    (C_CLS * HDIM)

#define LO_SCALE     256.0f
#define LO_INV_SCALE 0.00390625f

/* ------------------- scratch: device globals (no allocs) ------------------ */
__device__ float g_hidden[(size_t)NCROW * HDIM];
__device__ half  g_Xh[(size_t)NCROW * KX];
__device__ half  g_Xl[(size_t)NCROW * KX];
__device__ float g_Y[(size_t)NCROW * KX];
__device__ half  g_RHh[(size_t)NCROW * HDIM];
__device__ half  g_RHl[(size_t)NCROW * HDIM];
__device__ half  g_Hh[(size_t)NCROW * HDIM];
__device__ half  g_Hl[(size_t)NCROW * HDIM];
__device__ float g_U5[(size_t)NCROW * HDIM];
__device__ float g_O1[(size_t)NCROW * HDIM];
__device__ float g_S[CH];
__device__ float g_MS1[CH];
__device__ float g_MS2[CH];
__device__ half  g_Wch[(size_t)KX * KX];
__device__ half  g_Wcl[(size_t)KX * KX];
__device__ half  g_W5uh[HDIM * HDIM];
__device__ half  g_W5ul[HDIM * HDIM];
__device__ half  g_Woh[HDIM * 2 * HDIM];
__device__ half  g_Wol[HDIM * 2 * HDIM];
__device__ half  g_Ih[N_OBJ * HDIM];
__device__ half  g_Il[N_OBJ * HDIM];
__device__ float g_B2[N_OBJ * HDIM];
__device__ float g_Pcls[(size_t)C_CLS * N_OBJ * C_CLS];

/* ------------------------------ helpers ----------------------------------- */
__device__ __forceinline__ void split_store(float v, half* ph, half* pl)
{
    half hi = __float2half_rn(v);
    *ph = hi;
    *pl = __float2half_rn((v - __half2float(hi)) * LO_SCALE);
}

__device__ __forceinline__ unsigned smem_u32(const void* p)
{
    return (unsigned)__cvta_generic_to_shared(p);
}

__device__ __forceinline__ void ldsm4(unsigned* r, unsigned addr)
{
    asm volatile("ldmatrix.sync.aligned.m8n8.x4.shared.b16 {%0,%1,%2,%3},[%4];"
        : "=r"(r[0]), "=r"(r[1]), "=r"(r[2]), "=r"(r[3]) : "r"(addr));
}

__device__ __forceinline__ void mma16816(float* c, const unsigned* a, const unsigned* b)
{
    asm volatile("mma.sync.aligned.m16n8k16.row.col.f32.f16.f16.f32 "
        "{%0,%1,%2,%3},{%4,%5,%6,%7},{%8,%9},{%0,%1,%2,%3};"
        : "+f"(c[0]), "+f"(c[1]), "+f"(c[2]), "+f"(c[3])
        : "r"(a[0]), "r"(a[1]), "r"(a[2]), "r"(a[3]), "r"(b[0]), "r"(b[1]));
}

__device__ __forceinline__ void cp16(void* dst_smem, const void* src_gmem)
{
    unsigned s = smem_u32(dst_smem);
    asm volatile("cp.async.cg.shared.global [%0], [%1], 16;" :: "r"(s), "l"(src_gmem));
}

__device__ __forceinline__ void cp_commit()
{
    asm volatile("cp.async.commit_group;" ::: "memory");
}

__device__ __forceinline__ void cp_wait0()
{
    asm volatile("cp.async.wait_group 0;" ::: "memory");
}

/* ------------------------- weight concat + split -------------------------- */
__global__ void build_wcat(const float* __restrict__ w3w, const float* __restrict__ w3u,
                           const float* __restrict__ w4w, const float* __restrict__ w4u,
                           const float* __restrict__ w5w)
{
    int idx = blockIdx.x * blockDim.x + threadIdx.x;
    if (idx >= KX * KX) return;
    int o = idx / KX;
    int k = idx - o * KX;
    float v;
    if (o < 512) {
        v = (k < 1024) ? w3w[o * 1024 + k] : w3u[o * 512 + (k - 1024)];
    } else if (o < 1024) {
        int oo = o - 512;
        v = (k < 1024) ? w4w[oo * 1024 + k] : w4u[oo * 512 + (k - 1024)];
    } else {
        int oo = o - 1024;
        v = (k < 1024) ? w5w[oo * 1024 + k] : 0.0f;
    }
    split_store(v, &g_Wch[idx], &g_Wcl[idx]);
}

__global__ void split_f32(const float* __restrict__ src, half* __restrict__ dh,
                          half* __restrict__ dl, int n)
{
    int idx = blockIdx.x * blockDim.x + threadIdx.x;
    if (idx >= n) return;
    split_store(src[idx], &dh[idx], &dl[idx]);
}

/* ------------------- init hidden[n][c][h] = input[n][h] ------------------- */
__global__ void init_hidden(const float* __restrict__ input)
{
    size_t idx = (size_t)blockIdx.x * blockDim.x + threadIdx.x;
    int h = (int)(idx & (HDIM - 1));
    size_t m = idx >> 9;
    int n = (int)(m / C_CLS);
    g_hidden[idx] = input[(size_t)n * HDIM + h];
}

/* -------------------- S[c][h] = sum_n hidden[n][c][h] --------------------- */
__global__ void colsum_kernel()
{
    int idx = blockIdx.x * blockDim.x + threadIdx.x;
    float s = 0.f;
    #pragma unroll 4
    for (int n = 0; n < N_OBJ; n++) s += g_hidden[(size_t)n * CH + idx];
    g_S[idx] = s;
}

/* --------- MS1[d][h]=sum_c M[c][d]S[c][h] ; MS2[d][h]=sum_c M[d][c]S ------ */
__global__ void msprop_kernel(const float* __restrict__ M)
{
    int idx = blockIdx.x * blockDim.x + threadIdx.x;
    int d = idx / HDIM;
    int h = idx - d * HDIM;
    float s1 = 0.f, s2 = 0.f;
    for (int c = 0; c < C_CLS; c++) {
        float sv = g_S[c * HDIM + h];
        s1 += M[c * C_CLS + d] * sv;
        s2 += M[d * C_CLS + c] * sv;
    }
    g_MS1[idx] = s1;
    g_MS2[idx] = s2;
}

/* ------ prop + X build: X[(n,d)] = [MS1-M^T h | MS2-M h | hidden] (split) -- */
#define P_DT 32
#define P_HT 64
__global__ __launch_bounds__(256) void prop_kernel(const float* __restrict__ M)
{
    __shared__ float Hs[8][P_HT];
    __shared__ float M1s[8][P_DT];
    __shared__ float M2s[8][P_DT];
    int n  = blockIdx.z;
    int d0 = blockIdx.y * P_DT;
    int h0 = blockIdx.x * P_HT;
    int tid = threadIdx.x;
    int hx = tid & 31;
    int ty = tid >> 5;
    float a1[4][2] = {{0.f, 0.f}, {0.f, 0.f}, {0.f, 0.f}, {0.f, 0.f}};
    float a2[4][2] = {{0.f, 0.f}, {0.f, 0.f}, {0.f, 0.f}, {0.f, 0.f}};
    const float* Hn = g_hidden + (size_t)n * CH;

    for (int c0 = 0; c0 < C_CLS; c0 += 8) {
        #pragma unroll
        for (int l = 0; l < 2; l++) {
            int f = tid + l * 256;
            int cc = f >> 6;
            int hh = f & 63;
            int c = c0 + cc;
            Hs[cc][hh] = (c < C_CLS) ? Hn[(size_t)c * HDIM + h0 + hh] : 0.f;
        }
        {
            int cc = tid >> 5;
            int dd = tid & 31;
            int c = c0 + cc;
            int d = d0 + dd;
            bool ok = (c < C_CLS) && (d < C_CLS);
            M1s[cc][dd] = ok ? M[c * C_CLS + d] : 0.f;
            M2s[cc][dd] = ok ? M[d * C_CLS + c] : 0.f;
        }
        __syncthreads();
        #pragma unroll
        for (int cc = 0; cc < 8; cc++) {
            float hv0 = Hs[cc][hx];
            float hv1 = Hs[cc][hx + 32];
            #pragma unroll
            for (int i = 0; i < 4; i++) {
                float m1 = M1s[cc][ty * 4 + i];
                float m2 = M2s[cc][ty * 4 + i];
                a1[i][0] += m1 * hv0;
                a1[i][1] += m1 * hv1;
                a2[i][0] += m2 * hv0;
                a2[i][1] += m2 * hv1;
            }
        }
        __syncthreads();
    }
    #pragma unroll
    for (int i = 0; i < 4; i++) {
        int d = d0 + ty * 4 + i;
        if (d < C_CLS) {
            size_t r = (size_t)(n * C_CLS + d) * KX;
            #pragma unroll
            for (int q = 0; q < 2; q++) {
                int h = h0 + hx + q * 32;
                float v1 = g_MS1[(size_t)d * HDIM + h] - a1[i][q];
                float v2 = g_MS2[(size_t)d * HDIM + h] - a2[i][q];
                float hv = Hn[(size_t)d * HDIM + h];
                split_store(v1, &g_Xh[r + h],        &g_Xl[r + h]);
                split_store(v2, &g_Xh[r + 512 + h],  &g_Xl[r + 512 + h]);
                split_store(hv, &g_Xh[r + 1024 + h], &g_Xl[r + 1024 + h]);
            }
        }
    }
}

/* ----------- tensor-core GEMM  C[m][n] = sum_k A[m][k] * B[n][k] ----------- */
/* fp32 via fp16 3-product split with scaled-lo residues and per-K-chunk      */
/* accumulator draining (neutralizes tensor-core RZ-accumulation bias).       */
/* C = drained(ah*bh) + (ah*bl' + al'*bh) / LO_SCALE.                          */
#define GBM 128
#define GBN 128
#define GBK 32
#define SROW 40
#define SA_IDX(b, hl, r, c) (((((b) * 2 + (hl)) * GBM) + (r)) * SROW + (c))
#define SB_IDX(b, hl, r, c) (((((b) * 2 + (hl)) * GBN) + (r)) * SROW + (c))

__device__ __forceinline__ void gemm_load_stage(
    half* sA, half* sB, int s, int k0, int tid, int m0, int n0,
    const half* Ah, const half* Al, int lda,
    const half* Bh, const half* Bl, int ldb)
{
    #pragma unroll
    for (int t = 0; t < 2; t++) {
        int idx = tid + t * 256;
        int row = idx >> 2;
        int ck  = (idx & 3) * 8;
        cp16(&sA[SA_IDX(s, 0, row, ck)], Ah + (size_t)(m0 + row) * lda + k0 + ck);
        cp16(&sA[SA_IDX(s, 1, row, ck)], Al + (size_t)(m0 + row) * lda + k0 + ck);
        cp16(&sB[SB_IDX(s, 0, row, ck)], Bh + (size_t)(n0 + row) * ldb + k0 + ck);
        cp16(&sB[SB_IDX(s, 1, row, ck)], Bl + (size_t)(n0 + row) * ldb + k0 + ck);
    }
}

__global__ __launch_bounds__(256, 1) void gemm3(
    const half* __restrict__ Ah, const half* __restrict__ Al, int lda,
    const half* __restrict__ Bh, const half* __restrict__ Bl, int ldb,
    float* __restrict__ Cout, int ldc, int K)
{
    extern __shared__ half smem[];
    half* sA = smem;
    half* sB = smem + 2 * 2 * GBM * SROW;

    int tid = threadIdx.x;
    int warp = tid >> 5;
    int lane = tid & 31;
    int wm = warp >> 2;
    int wn = warp & 3;
    int m0 = blockIdx.x * GBM;
    int n0 = blockIdx.y * GBN;

    float acc[4][4][4];   /* hi*hi, drained each K-chunk */
    float accS[4][4][4];  /* rn drain target */
    float acl[4][4][4];   /* hi*lo' + lo'*hi (scaled by LO_SCALE) */
    #pragma unroll
    for (int i = 0; i < 4; i++) {
        #pragma unroll
        for (int j = 0; j < 4; j++) {
            #pragma unroll
            for (int q = 0; q < 4; q++) {
                acc[i][j][q]  = 0.f;
                accS[i][j][q] = 0.f;
                acl[i][j][q]  = 0.f;
            }
        }
    }

    gemm_load_stage(sA, sB, 0, 0, tid, m0, n0, Ah, Al, lda, Bh, Bl, ldb);
    cp_commit();

    int nit = K / GBK;
    for (int it = 0; it < nit; it++) {
        int cur = it & 1;
        cp_wait0();
        __syncthreads();
        if (it + 1 < nit) {
            gemm_load_stage(sA, sB, cur ^ 1, (it + 1) * GBK, tid, m0, n0,
                            Ah, Al, lda, Bh, Bl, ldb);
            cp_commit();
        }
        #pragma unroll
        for (int ks = 0; ks < 2; ks++) {
            int kk = ks * 16;
            unsigned bhf[2][4];
            unsigned blf[2][4];
            #pragma unroll
            for (int p = 0; p < 2; p++) {
                int nn = wn * 32 + p * 16 + ((lane >> 4) << 3) + (lane & 7);
                int kb = kk + (((lane >> 3) & 1) << 3);
                ldsm4(bhf[p], smem_u32(&sB[SB_IDX(cur, 0, nn, kb)]));
                ldsm4(blf[p], smem_u32(&sB[SB_IDX(cur, 1, nn, kb)]));
            }
            #pragma unroll
            for (int mf = 0; mf < 4; mf++) {
                int mm = wm * 64 + mf * 16 + (lane & 15);
                int ka = kk + ((lane >> 4) << 3);
                unsigned ahf[4];
                unsigned alf[4];
                ldsm4(ahf, smem_u32(&sA[SA_IDX(cur, 0, mm, ka)]));
                ldsm4(alf, smem_u32(&sA[SA_IDX(cur, 1, mm, ka)]));
                #pragma unroll
                for (int nf = 0; nf < 4; nf++) {
                    const unsigned* bh = &bhf[nf >> 1][(nf & 1) * 2];
                    const unsigned* bl = &blf[nf >> 1][(nf & 1) * 2];
                    mma16816(acc[mf][nf], ahf, bh);
                    mma16816(acl[mf][nf], ahf, bl);
                    mma16816(acl[mf][nf], alf, bh);
                }
            }
        }
        /* drain hi*hi accumulator with rn adds; reset MMA accumulator */
        #pragma unroll
        for (int mf = 0; mf < 4; mf++) {
            #pragma unroll
            for (int nf = 0; nf < 4; nf++) {
                #pragma unroll
                for (int q = 0; q < 4; q++) {
                    accS[mf][nf][q] += acc[mf][nf][q];
                    acc[mf][nf][q] = 0.f;
                }
            }
        }
        __syncthreads();
    }

    int r = lane >> 2;
    int cb = (lane & 3) * 2;
    #pragma unroll
    for (int mf = 0; mf < 4; mf++) {
        #pragma unroll
        for (int nf = 0; nf < 4; nf++) {
            float* Cp = Cout + (size_t)(m0 + wm * 64 + mf * 16 + r) * ldc
                             + (n0 + wn * 32 + nf * 8 + cb);
            Cp[0] = accS[mf][nf][0] + acl[mf][nf][0] * LO_INV_SCALE;
            Cp[1] = accS[mf][nf][1] + acl[mf][nf][1] * LO_INV_SCALE;
            Cp += (size_t)8 * ldc;
            Cp[0] = accS[mf][nf][2] + acl[mf][nf][2] * LO_INV_SCALE;
            Cp[1] = accS[mf][nf][3] + acl[mf][nf][3] * LO_INV_SCALE;
        }
    }
}

/* ------------------------------ pointwise --------------------------------- */
__device__ __forceinline__ float sigmoidf_(float x)
{
    return 1.f / (1.f + expf(-x));
}

__global__ void pw_rv(const float* __restrict__ b4w, const float* __restrict__ b4u)
{
    size_t idx = (size_t)blockIdx.x * blockDim.x + threadIdx.x;
    int h = (int)(idx & (HDIM - 1));
    size_t m = idx >> 9;
    float r = g_Y[m * KX + 512 + h] + b4w[h] + b4u[h];
    float rh = sigmoidf_(r) * g_hidden[idx];
    split_store(rh, &g_RHh[idx], &g_RHl[idx]);
}

__global__ void pw_update(const float* __restrict__ b3w, const float* __restrict__ b3u,
                          const float* __restrict__ b5w, const float* __restrict__ b5u)
{
    size_t idx = (size_t)blockIdx.x * blockDim.x + threadIdx.x;
    int h = (int)(idx & (HDIM - 1));
    size_t m = idx >> 9;
    float z  = sigmoidf_(g_Y[m * KX + h] + b3w[h] + b3u[h]);
    float hv = tanhf(g_Y[m * KX + 1024 + h] + b5w[h] + g_U5[idx] + b5u[h]);
    float hp = g_hidden[idx];
    float nh = (1.f - z) * hp + z * hv;
    g_hidden[idx] = nh;
    split_store(nh, &g_Hh[idx], &g_Hl[idx]);
}

__global__ void pw_relu(const float* __restrict__ bout)
{
    size_t idx = (size_t)blockIdx.x * blockDim.x + threadIdx.x;
    int h = (int)(idx & (HDIM - 1));
    size_t m = idx >> 9;
    int n = (int)(m / C_CLS);
    float v = g_O1[idx] + g_B2[n * HDIM + h] + bout[h];
    g_O1[idx] = v > 0.f ? v : 0.f;
}

/* --------------------- classifier: split-K over c ------------------------- */
__global__ __launch_bounds__(160) void cls_partial(const float* __restrict__ wcls)
{
    __shared__ float O1s[32][64];
    int nt = blockIdx.x;
    int ks = blockIdx.y;
    int j = threadIdx.x;
    float acc[32];
    #pragma unroll
    for (int nn = 0; nn < 32; nn++) acc[nn] = 0.f;

    for (int kb = 0; kb < 512; kb += 64) {
        for (int f = threadIdx.x; f < 32 * 64; f += 160) {
            int nn = f >> 6;
            int kk = f & 63;
            O1s[nn][kk] = g_O1[(size_t)(nt * 32 + nn) * CH + ks * 512 + kb + kk];
        }
        __syncthreads();
        if (j < C_CLS) {
            const float* wrow = wcls + (size_t)j * CH + ks * 512 + kb;
            #pragma unroll 4
            for (int kk = 0; kk < 64; kk += 4) {
                float4 w = *(const float4*)(wrow + kk);
                #pragma unroll
                for (int nn = 0; nn < 32; nn++) {
                    float4 o = *(const float4*)&O1s[nn][kk];
                    acc[nn] += w.x * o.x + w.y * o.y + w.z * o.z + w.w * o.w;
                }
            }
        }
        __syncthreads();
    }
    if (j < C_CLS) {
        #pragma unroll
        for (int nn = 0; nn < 32; nn++)
            g_Pcls[((size_t)ks * N_OBJ + nt * 32 + nn) * C_CLS + j] = acc[nn];
    }
}

__global__ void cls_reduce(const float* __restrict__ bcls, float* __restrict__ out)
{
    int idx = blockIdx.x * blockDim.x + threadIdx.x;
    if (idx >= N_OBJ * C_CLS) return;
    int n = idx / C_CLS;
    int j = idx - n * C_CLS;
    float s = bcls[j];
    for (int ks = 0; ks < C_CLS; ks++)
        s += g_Pcls[((size_t)ks * N_OBJ + n) * C_CLS + j];
    out[idx] = s;
}

/* --------------------------------------------------------------------------- */
extern "C" void kernel_launch(void* const* d_in, const int* in_sizes, int n_in,
                              void* d_out, int out_size)
{
    const float* input  = (const float*)d_in[0];
    const float* matrix = (const float*)d_in[1];
    const float* w3w = (const float*)d_in[2];
    const float* b3w = (const float*)d_in[3];
    const float* w3u = (const float*)d_in[4];
    const float* b3u = (const float*)d_in[5];
    const float* w4w = (const float*)d_in[6];
    const float* b4w = (const float*)d_in[7];
    const float* w4u = (const float*)d_in[8];
    const float* b4u = (const float*)d_in[9];
    const float* w5w = (const float*)d_in[10];
    const float* b5w = (const float*)d_in[11];
    const float* w5u = (const float*)d_in[12];
    const float* b5u = (const float*)d_in[13];
    const float* wout = (const float*)d_in[14];
    const float* bout = (const float*)d_in[15];
    const float* wcls = (const float*)d_in[16];
    const float* bcls = (const float*)d_in[17];
    float* out = (float*)d_out;

    void* tmp = 0;
    float* pY;
    float* pU5;
    float* pO1;
    float* pB2;
    half* pXh;
    half* pXl;
    half* pWch;
    half* pWcl;
    half* pRHh;
    half* pRHl;
    half* pHh;
    half* pHl;
    half* pW5uh;
    half* pW5ul;
    half* pWoh;
    half* pWol;
    half* pIh;
    half* pIl;

    cudaGetSymbolAddress(&tmp, g_Y);     pY    = (float*)tmp;
    cudaGetSymbolAddress(&tmp, g_U5);    pU5   = (float*)tmp;
    cudaGetSymbolAddress(&tmp, g_O1);    pO1   = (float*)tmp;
    cudaGetSymbolAddress(&tmp, g_B2);    pB2   = (float*)tmp;
    cudaGetSymbolAddress(&tmp, g_Xh);    pXh   = (half*)tmp;
    cudaGetSymbolAddress(&tmp, g_Xl);    pXl   = (half*)tmp;
    cudaGetSymbolAddress(&tmp, g_Wch);   pWch  = (half*)tmp;
    cudaGetSymbolAddress(&tmp, g_Wcl);   pWcl  = (half*)tmp;
    cudaGetSymbolAddress(&tmp, g_RHh);   pRHh  = (half*)tmp;
    cudaGetSymbolAddress(&tmp, g_RHl);   pRHl  = (half*)tmp;
    cudaGetSymbolAddress(&tmp, g_Hh);    pHh   = (half*)tmp;
    cudaGetSymbolAddress(&tmp, g_Hl);    pHl   = (half*)tmp;
    cudaGetSymbolAddress(&tmp, g_W5uh);  pW5uh = (half*)tmp;
    cudaGetSymbolAddress(&tmp, g_W5ul);  pW5ul = (half*)tmp;
    cudaGetSymbolAddress(&tmp, g_Woh);   pWoh  = (half*)tmp;
    cudaGetSymbolAddress(&tmp, g_Wol);   pWol  = (half*)tmp;
    cudaGetSymbolAddress(&tmp, g_Ih);    pIh   = (half*)tmp;
    cudaGetSymbolAddress(&tmp, g_Il);    pIl   = (half*)tmp;

    const int GEMM_SMEM = 2 * 2 * (GBM + GBN) * SROW * (int)sizeof(half);
    cudaFuncSetAttribute(gemm3, cudaFuncAttributeMaxDynamicSharedMemorySize, GEMM_SMEM);

    const int PW_BLOCKS = (int)(((size_t)NCROW * HDIM) / 256);
    const int CH_BLOCKS = CH / 256;

    build_wcat<<<(KX * KX + 255) / 256, 256>>>(w3w, w3u, w4w, w4u, w5w);
    split_f32<<<(HDIM * HDIM + 255) / 256, 256>>>(w5u, pW5uh, pW5ul, HDIM * HDIM);
    split_f32<<<(HDIM * 2 * HDIM + 255) / 256, 256>>>(wout, pWoh, pWol, HDIM * 2 * HDIM);
    split_f32<<<(N_OBJ * HDIM + 255) / 256, 256>>>(input, pIh, pIl, N_OBJ * HDIM);

    /* B2 = input @ Wo2^T  (input-cols 512..1023 of w_out) */
    gemm3<<<dim3(N_OBJ / GBM, HDIM / GBN), 256, GEMM_SMEM>>>(
        pIh, pIl, HDIM, pWoh + 512, pWol + 512, 2 * HDIM, pB2, HDIM, HDIM);

    init_hidden<<<PW_BLOCKS, 256>>>(input);

    for (int t = 0; t < 3; t++) {
        colsum_kernel<<<CH_BLOCKS, 256>>>();
        msprop_kernel<<<CH_BLOCKS, 256>>>(matrix);
        prop_kernel<<<dim3(HDIM / P_HT, (C_CLS + P_DT - 1) / P_DT, N_OBJ), 256>>>(matrix);
        /* Y = X @ Wcat^T : [38656,1536] x [1536,1536] */
        gemm3<<<dim3(NCROW / GBM, KX / GBN), 256, GEMM_SMEM>>>(
            pXh, pXl, KX, pWch, pWcl, KX, pY, KX, KX);
        pw_rv<<<PW_BLOCKS, 256>>>(b4w, b4u);
        /* U5 = (rv*h) @ W5u^T */
        gemm3<<<dim3(NCROW / GBM, HDIM / GBN), 256, GEMM_SMEM>>>(
            pRHh, pRHl, HDIM, pW5uh, pW5ul, HDIM, pU5, HDIM, HDIM);
        pw_update<<<PW_BLOCKS, 256>>>(b3w, b3u, b5w, b5u);
    }

    /* O1 = hidden @ Wo1^T  (input-cols 0..511 of w_out) */
    gemm3<<<dim3(NCROW / GBM, HDIM / GBN), 256, GEMM_SMEM>>>(
        pHh, pHl, HDIM, pWoh, pWol, 2 * HDIM, pO1, HDIM, HDIM);
    pw_relu<<<PW_BLOCKS, 256>>>(bout);

    cls_partial<<<dim3(N_OBJ / 32, C_CLS), 160>>>(wcls);
    cls_reduce<<<(N_OBJ * C_CLS + 255) / 256, 256>>>(bcls, out);
}

// round 9
// speedup vs baseline: 1.0002x; 1.0002x over previous
#include <cuda_runtime.h>
#include <cuda_fp16.h>
#include <math.h>

#define N_OBJ 256
#define C_CLS 151
#define HDIM  512
#define NCROW (N_OBJ * C_CLS)
#define KX    1536
#define CH    (C_CLS * HDIM)

#define LO_SCALE     256.0f
#define LO_INV_SCALE 0.00390625f

/* ------------------- scratch: device globals (no allocs) ------------------ */
__device__ float g_hidden[(size_t)NCROW * HDIM];
__device__ half  g_Xh[(size_t)NCROW * KX];
__device__ half  g_Xl[(size_t)NCROW * KX];
__device__ float g_Y[(size_t)NCROW * KX];
__device__ half  g_RHh[(size_t)NCROW * HDIM];
__device__ half  g_RHl[(size_t)NCROW * HDIM];
__device__ half  g_Hh[(size_t)NCROW * HDIM];
__device__ half  g_Hl[(size_t)NCROW * HDIM];
__device__ float g_U5[(size_t)NCROW * HDIM];
__device__ float g_O1[(size_t)NCROW * HDIM];
__device__ float g_S[CH];
__device__ float g_MS1[CH];
__device__ float g_MS2[CH];
__device__ half  g_Wch[(size_t)KX * KX];
__device__ half  g_Wcl[(size_t)KX * KX];
__device__ half  g_W5uh[HDIM * HDIM];
__device__ half  g_W5ul[HDIM * HDIM];
__device__ half  g_Woh[HDIM * 2 * HDIM];
__device__ half  g_Wol[HDIM * 2 * HDIM];
__device__ half  g_Ih[N_OBJ * HDIM];
__device__ half  g_Il[N_OBJ * HDIM];
__device__ float g_B2[N_OBJ * HDIM];
__device__ float g_Pcls[(size_t)C_CLS * N_OBJ * C_CLS];

/* ------------------------------ helpers ----------------------------------- */
__device__ __forceinline__ void split_store(float v, half* ph, half* pl)
{
    half hi = __float2half_rn(v);
    *ph = hi;
    *pl = __float2half_rn((v - __half2float(hi)) * LO_SCALE);
}

__device__ __forceinline__ unsigned smem_u32(const void* p)
{
    return (unsigned)__cvta_generic_to_shared(p);
}

__device__ __forceinline__ void ldsm4(unsigned* r, unsigned addr)
{
    asm volatile("ldmatrix.sync.aligned.m8n8.x4.shared.b16 {%0,%1,%2,%3},[%4];"
        : "=r"(r[0]), "=r"(r[1]), "=r"(r[2]), "=r"(r[3]) : "r"(addr));
}

__device__ __forceinline__ void mma16816(float* c, const unsigned* a, const unsigned* b)
{
    asm volatile("mma.sync.aligned.m16n8k16.row.col.f32.f16.f16.f32 "
        "{%0,%1,%2,%3},{%4,%5,%6,%7},{%8,%9},{%0,%1,%2,%3};"
        : "+f"(c[0]), "+f"(c[1]), "+f"(c[2]), "+f"(c[3])
        : "r"(a[0]), "r"(a[1]), "r"(a[2]), "r"(a[3]), "r"(b[0]), "r"(b[1]));
}

__device__ __forceinline__ void cp16(void* dst_smem, const void* src_gmem)
{
    unsigned s = smem_u32(dst_smem);
    asm volatile("cp.async.cg.shared.global [%0], [%1], 16;" :: "r"(s), "l"(src_gmem));
}

__device__ __forceinline__ void cp_commit()
{
    asm volatile("cp.async.commit_group;" ::: "memory");
}

__device__ __forceinline__ void cp_wait0()
{
    asm volatile("cp.async.wait_group 0;" ::: "memory");
}

/* ------------------------- weight concat + split -------------------------- */
__global__ void build_wcat(const float* __restrict__ w3w, const float* __restrict__ w3u,
                           const float* __restrict__ w4w, const float* __restrict__ w4u,
                           const float* __restrict__ w5w)
{
    int idx = blockIdx.x * blockDim.x + threadIdx.x;
    if (idx >= KX * KX) return;
    int o = idx / KX;
    int k = idx - o * KX;
    float v;
    if (o < 512) {
        v = (k < 1024) ? w3w[o * 1024 + k] : w3u[o * 512 + (k - 1024)];
    } else if (o < 1024) {
        int oo = o - 512;
        v = (k < 1024) ? w4w[oo * 1024 + k] : w4u[oo * 512 + (k - 1024)];
    } else {
        int oo = o - 1024;
        v = (k < 1024) ? w5w[oo * 1024 + k] : 0.0f;
    }
    split_store(v, &g_Wch[idx], &g_Wcl[idx]);
}

__global__ void split_f32(const float* __restrict__ src, half* __restrict__ dh,
                          half* __restrict__ dl, int n)
{
    int idx = blockIdx.x * blockDim.x + threadIdx.x;
    if (idx >= n) return;
    split_store(src[idx], &dh[idx], &dl[idx]);
}

/* ------------------- init hidden[n][c][h] = input[n][h] ------------------- */
__global__ void init_hidden(const float* __restrict__ input)
{
    size_t idx = (size_t)blockIdx.x * blockDim.x + threadIdx.x;
    int h = (int)(idx & (HDIM - 1));
    size_t m = idx >> 9;
    int n = (int)(m / C_CLS);
    g_hidden[idx] = input[(size_t)n * HDIM + h];
}

/* -------------------- S[c][h] = sum_n hidden[n][c][h] --------------------- */
__global__ void colsum_kernel()
{
    int idx = blockIdx.x * blockDim.x + threadIdx.x;
    float s = 0.f;
    #pragma unroll 4
    for (int n = 0; n < N_OBJ; n++) s += g_hidden[(size_t)n * CH + idx];
    g_S[idx] = s;
}

/* --------- MS1[d][h]=sum_c M[c][d]S[c][h] ; MS2[d][h]=sum_c M[d][c]S ------ */
__global__ void msprop_kernel(const float* __restrict__ M)
{
    int idx = blockIdx.x * blockDim.x + threadIdx.x;
    int d = idx / HDIM;
    int h = idx - d * HDIM;
    float s1 = 0.f, s2 = 0.f;
    for (int c = 0; c < C_CLS; c++) {
        float sv = g_S[c * HDIM + h];
        s1 += M[c * C_CLS + d] * sv;
        s2 += M[d * C_CLS + c] * sv;
    }
    g_MS1[idx] = s1;
    g_MS2[idx] = s2;
}

/* ------ prop + X build: X[(n,d)] = [MS1-M^T h | MS2-M h | hidden] (split) -- */
#define P_DT 32
#define P_HT 64
__global__ __launch_bounds__(256) void prop_kernel(const float* __restrict__ M)
{
    __shared__ float Hs[8][P_HT];
    __shared__ float M1s[8][P_DT];
    __shared__ float M2s[8][P_DT];
    int n  = blockIdx.z;
    int d0 = blockIdx.y * P_DT;
    int h0 = blockIdx.x * P_HT;
    int tid = threadIdx.x;
    int hx = tid & 31;
    int ty = tid >> 5;
    float a1[4][2] = {{0.f, 0.f}, {0.f, 0.f}, {0.f, 0.f}, {0.f, 0.f}};
    float a2[4][2] = {{0.f, 0.f}, {0.f, 0.f}, {0.f, 0.f}, {0.f, 0.f}};
    const float* Hn = g_hidden + (size_t)n * CH;

    for (int c0 = 0; c0 < C_CLS; c0 += 8) {
        #pragma unroll
        for (int l = 0; l < 2; l++) {
            int f = tid + l * 256;
            int cc = f >> 6;
            int hh = f & 63;
            int c = c0 + cc;
            Hs[cc][hh] = (c < C_CLS) ? Hn[(size_t)c * HDIM + h0 + hh] : 0.f;
        }
        {
            int cc = tid >> 5;
            int dd = tid & 31;
            int c = c0 + cc;
            int d = d0 + dd;
            bool ok = (c < C_CLS) && (d < C_CLS);
            M1s[cc][dd] = ok ? M[c * C_CLS + d] : 0.f;
            M2s[cc][dd] = ok ? M[d * C_CLS + c] : 0.f;
        }
        __syncthreads();
        #pragma unroll
        for (int cc = 0; cc < 8; cc++) {
            float hv0 = Hs[cc][hx];
            float hv1 = Hs[cc][hx + 32];
            #pragma unroll
            for (int i = 0; i < 4; i++) {
                float m1 = M1s[cc][ty * 4 + i];
                float m2 = M2s[cc][ty * 4 + i];
                a1[i][0] += m1 * hv0;
                a1[i][1] += m1 * hv1;
                a2[i][0] += m2 * hv0;
                a2[i][1] += m2 * hv1;
            }
        }
        __syncthreads();
    }
    #pragma unroll
    for (int i = 0; i < 4; i++) {
        int d = d0 + ty * 4 + i;
        if (d < C_CLS) {
            size_t r = (size_t)(n * C_CLS + d) * KX;
            #pragma unroll
            for (int q = 0; q < 2; q++) {
                int h = h0 + hx + q * 32;
                float v1 = g_MS1[(size_t)d * HDIM + h] - a1[i][q];
                float v2 = g_MS2[(size_t)d * HDIM + h] - a2[i][q];
                float hv = Hn[(size_t)d * HDIM + h];
                split_store(v1, &g_Xh[r + h],        &g_Xl[r + h]);
                split_store(v2, &g_Xh[r + 512 + h],  &g_Xl[r + 512 + h]);
                split_store(hv, &g_Xh[r + 1024 + h], &g_Xl[r + 1024 + h]);
            }
        }
    }
}

/* ----------- tensor-core GEMM  C[m][n] = sum_k A[m][k] * B[n][k] ----------- */
/* fp32 via fp16 3-product split with scaled-lo residues and per-K-chunk      */
/* drain of the hi*hi MMA accumulator into a SEPARATE rn-add register sum     */
/* (accS). C = accS + acl / LO_SCALE.                                         */
/* MMA issue order: per mf, three separate nf-passes so same-accumulator RAW  */
/* writes are 4 MMAs apart instead of back-to-back.                           */
#define GBM 128
#define GBN 128
#define GBK 32
#define SROW 40
#define SA_IDX(b, hl, r, c) (((((b) * 2 + (hl)) * GBM) + (r)) * SROW + (c))
#define SB_IDX(b, hl, r, c) (((((b) * 2 + (hl)) * GBN) + (r)) * SROW + (c))

__device__ __forceinline__ void gemm_load_stage(
    half* sA, half* sB, int s, int k0, int tid, int m0, int n0,
    const half* Ah, const half* Al, int lda,
    const half* Bh, const half* Bl, int ldb)
{
    #pragma unroll
    for (int t = 0; t < 2; t++) {
        int idx = tid + t * 256;
        int row = idx >> 2;
        int ck  = (idx & 3) * 8;
        cp16(&sA[SA_IDX(s, 0, row, ck)], Ah + (size_t)(m0 + row) * lda + k0 + ck);
        cp16(&sA[SA_IDX(s, 1, row, ck)], Al + (size_t)(m0 + row) * lda + k0 + ck);
        cp16(&sB[SB_IDX(s, 0, row, ck)], Bh + (size_t)(n0 + row) * ldb + k0 + ck);
        cp16(&sB[SB_IDX(s, 1, row, ck)], Bl + (size_t)(n0 + row) * ldb + k0 + ck);
    }
}

__global__ __launch_bounds__(256, 1) void gemm3(
    const half* __restrict__ Ah, const half* __restrict__ Al, int lda,
    const half* __restrict__ Bh, const half* __restrict__ Bl, int ldb,
    float* __restrict__ Cout, int ldc, int K)
{
    extern __shared__ half smem[];
    half* sA = smem;
    half* sB = smem + 2 * 2 * GBM * SROW;

    int tid = threadIdx.x;
    int warp = tid >> 5;
    int lane = tid & 31;
    int wm = warp >> 2;
    int wn = warp & 3;
    int m0 = blockIdx.x * GBM;
    int n0 = blockIdx.y * GBN;

    float acc[4][4][4];   /* hi*hi, drained each K-chunk */
    float accS[4][4][4];  /* rn drain target (never an MMA accumulator) */
    float acl[4][4][4];   /* hi*lo' + lo'*hi (scaled by LO_SCALE) */
    #pragma unroll
    for (int i = 0; i < 4; i++) {
        #pragma unroll
        for (int j = 0; j < 4; j++) {
            #pragma unroll
            for (int q = 0; q < 4; q++) {
                acc[i][j][q]  = 0.f;
                accS[i][j][q] = 0.f;
                acl[i][j][q]  = 0.f;
            }
        }
    }

    gemm_load_stage(sA, sB, 0, 0, tid, m0, n0, Ah, Al, lda, Bh, Bl, ldb);
    cp_commit();

    int nit = K / GBK;
    for (int it = 0; it < nit; it++) {
        int cur = it & 1;
        cp_wait0();
        __syncthreads();
        if (it + 1 < nit) {
            gemm_load_stage(sA, sB, cur ^ 1, (it + 1) * GBK, tid, m0, n0,
                            Ah, Al, lda, Bh, Bl, ldb);
            cp_commit();
        }
        #pragma unroll
        for (int ks = 0; ks < 2; ks++) {
            int kk = ks * 16;
            unsigned bhf[2][4];
            unsigned blf[2][4];
            #pragma unroll
            for (int p = 0; p < 2; p++) {
                int nn = wn * 32 + p * 16 + ((lane >> 4) << 3) + (lane & 7);
                int kb = kk + (((lane >> 3) & 1) << 3);
                ldsm4(bhf[p], smem_u32(&sB[SB_IDX(cur, 0, nn, kb)]));
                ldsm4(blf[p], smem_u32(&sB[SB_IDX(cur, 1, nn, kb)]));
            }
            #pragma unroll
            for (int mf = 0; mf < 4; mf++) {
                int mm = wm * 64 + mf * 16 + (lane & 15);
                int ka = kk + ((lane >> 4) << 3);
                unsigned ahf[4];
                unsigned alf[4];
                ldsm4(ahf, smem_u32(&sA[SA_IDX(cur, 0, mm, ka)]));
                ldsm4(alf, smem_u32(&sA[SA_IDX(cur, 1, mm, ka)]));
                /* pass 1: acc += ah*bh (4 independent accumulators) */
                #pragma unroll
                for (int nf = 0; nf < 4; nf++)
                    mma16816(acc[mf][nf], ahf, &bhf[nf >> 1][(nf & 1) * 2]);
                /* pass 2: acl += ah*bl' */
                #pragma unroll
                for (int nf = 0; nf < 4; nf++)
                    mma16816(acl[mf][nf], ahf, &blf[nf >> 1][(nf & 1) * 2]);
                /* pass 3: acl += al'*bh (RAW vs pass 2 is 4 MMAs apart) */
                #pragma unroll
                for (int nf = 0; nf < 4; nf++)
                    mma16816(acl[mf][nf], alf, &bhf[nf >> 1][(nf & 1) * 2]);
            }
        }
        /* drain hi*hi chunk into rn-add register sum; reset MMA accumulator */
        #pragma unroll
        for (int mf = 0; mf < 4; mf++) {
            #pragma unroll
            for (int nf = 0; nf < 4; nf++) {
                #pragma unroll
                for (int q = 0; q < 4; q++) {
                    accS[mf][nf][q] += acc[mf][nf][q];
                    acc[mf][nf][q] = 0.f;
                }
            }
        }
        __syncthreads();
    }

    int r = lane >> 2;
    int cb = (lane & 3) * 2;
    #pragma unroll
    for (int mf = 0; mf < 4; mf++) {
        #pragma unroll
        for (int nf = 0; nf < 4; nf++) {
            float* Cp = Cout + (size_t)(m0 + wm * 64 + mf * 16 + r) * ldc
                             + (n0 + wn * 32 + nf * 8 + cb);
            Cp[0] = accS[mf][nf][0] + acl[mf][nf][0] * LO_INV_SCALE;
            Cp[1] = accS[mf][nf][1] + acl[mf][nf][1] * LO_INV_SCALE;
            Cp += (size_t)8 * ldc;
            Cp[0] = accS[mf][nf][2] + acl[mf][nf][2] * LO_INV_SCALE;
            Cp[1] = accS[mf][nf][3] + acl[mf][nf][3] * LO_INV_SCALE;
        }
    }
}

/* ------------------------------ pointwise --------------------------------- */
__device__ __forceinline__ float sigmoidf_(float x)
{
    return 1.f / (1.f + expf(-x));
}

__global__ void pw_rv(const float* __restrict__ b4w, const float* __restrict__ b4u)
{
    size_t idx = (size_t)blockIdx.x * blockDim.x + threadIdx.x;
    int h = (int)(idx & (HDIM - 1));
    size_t m = idx >> 9;
    float r = g_Y[m * KX + 512 + h] + b4w[h] + b4u[h];
    float rh = sigmoidf_(r) * g_hidden[idx];
    split_store(rh, &g_RHh[idx], &g_RHl[idx]);
}

__global__ void pw_update(const float* __restrict__ b3w, const float* __restrict__ b3u,
                          const float* __restrict__ b5w, const float* __restrict__ b5u)
{
    size_t idx = (size_t)blockIdx.x * blockDim.x + threadIdx.x;
    int h = (int)(idx & (HDIM - 1));
    size_t m = idx >> 9;
    float z  = sigmoidf_(g_Y[m * KX + h] + b3w[h] + b3u[h]);
    float hv = tanhf(g_Y[m * KX + 1024 + h] + b5w[h] + g_U5[idx] + b5u[h]);
    float hp = g_hidden[idx];
    float nh = (1.f - z) * hp + z * hv;
    g_hidden[idx] = nh;
    split_store(nh, &g_Hh[idx], &g_Hl[idx]);
}

__global__ void pw_relu(const float* __restrict__ bout)
{
    size_t idx = (size_t)blockIdx.x * blockDim.x + threadIdx.x;
    int h = (int)(idx & (HDIM - 1));
    size_t m = idx >> 9;
    int n = (int)(m / C_CLS);
    float v = g_O1[idx] + g_B2[n * HDIM + h] + bout[h];
    g_O1[idx] = v > 0.f ? v : 0.f;
}

/* --------------------- classifier: split-K over c ------------------------- */
__global__ __launch_bounds__(160) void cls_partial(const float* __restrict__ wcls)
{
    __shared__ float O1s[32][64];
    int nt = blockIdx.x;
    int ks = blockIdx.y;
    int j = threadIdx.x;
    float acc[32];
    #pragma unroll
    for (int nn = 0; nn < 32; nn++) acc[nn] = 0.f;

    for (int kb = 0; kb < 512; kb += 64) {
        for (int f = threadIdx.x; f < 32 * 64; f += 160) {
            int nn = f >> 6;
            int kk = f & 63;
            O1s[nn][kk] = g_O1[(size_t)(nt * 32 + nn) * CH + ks * 512 + kb + kk];
        }
        __syncthreads();
        if (j < C_CLS) {
            const float* wrow = wcls + (size_t)j * CH + ks * 512 + kb;
            #pragma unroll 4
            for (int kk = 0; kk < 64; kk += 4) {
                float4 w = *(const float4*)(wrow + kk);
                #pragma unroll
                for (int nn = 0; nn < 32; nn++) {
                    float4 o = *(const float4*)&O1s[nn][kk];
                    acc[nn] += w.x * o.x + w.y * o.y + w.z * o.z + w.w * o.w;
                }
            }
        }
        __syncthreads();
    }
    if (j < C_CLS) {
        #pragma unroll
        for (int nn = 0; nn < 32; nn++)
            g_Pcls[((size_t)ks * N_OBJ + nt * 32 + nn) * C_CLS + j] = acc[nn];
    }
}

__global__ void cls_reduce(const float* __restrict__ bcls, float* __restrict__ out)
{
    int idx = blockIdx.x * blockDim.x + threadIdx.x;
    if (idx >= N_OBJ * C_CLS) return;
    int n = idx / C_CLS;
    int j = idx - n * C_CLS;
    float s = bcls[j];
    for (int ks = 0; ks < C_CLS; ks++)
        s += g_Pcls[((size_t)ks * N_OBJ + n) * C_CLS + j];
    out[idx] = s;
}

/* --------------------------------------------------------------------------- */
extern "C" void kernel_launch(void* const* d_in, const int* in_sizes, int n_in,
                              void* d_out, int out_size)
{
    const float* input  = (const float*)d_in[0];
    const float* matrix = (const float*)d_in[1];
    const float* w3w = (const float*)d_in[2];
    const float* b3w = (const float*)d_in[3];
    const float* w3u = (const float*)d_in[4];
    const float* b3u = (const float*)d_in[5];
    const float* w4w = (const float*)d_in[6];
    const float* b4w = (const float*)d_in[7];
    const float* w4u = (const float*)d_in[8];
    const float* b4u = (const float*)d_in[9];
    const float* w5w = (const float*)d_in[10];
    const float* b5w = (const float*)d_in[11];
    const float* w5u = (const float*)d_in[12];
    const float* b5u = (const float*)d_in[13];
    const float* wout = (const float*)d_in[14];
    const float* bout = (const float*)d_in[15];
    const float* wcls = (const float*)d_in[16];
    const float* bcls = (const float*)d_in[17];
    float* out = (float*)d_out;

    void* tmp = 0;
    float* pY;
    float* pU5;
    float* pO1;
    float* pB2;
    half* pXh;
    half* pXl;
    half* pWch;
    half* pWcl;
    half* pRHh;
    half* pRHl;
    half* pHh;
    half* pHl;
    half* pW5uh;
    half* pW5ul;
    half* pWoh;
    half* pWol;
    half* pIh;
    half* pIl;

    cudaGetSymbolAddress(&tmp, g_Y);     pY    = (float*)tmp;
    cudaGetSymbolAddress(&tmp, g_U5);    pU5   = (float*)tmp;
    cudaGetSymbolAddress(&tmp, g_O1);    pO1   = (float*)tmp;
    cudaGetSymbolAddress(&tmp, g_B2);    pB2   = (float*)tmp;
    cudaGetSymbolAddress(&tmp, g_Xh);    pXh   = (half*)tmp;
    cudaGetSymbolAddress(&tmp, g_Xl);    pXl   = (half*)tmp;
    cudaGetSymbolAddress(&tmp, g_Wch);   pWch  = (half*)tmp;
    cudaGetSymbolAddress(&tmp, g_Wcl);   pWcl  = (half*)tmp;
    cudaGetSymbolAddress(&tmp, g_RHh);   pRHh  = (half*)tmp;
    cudaGetSymbolAddress(&tmp, g_RHl);   pRHl  = (half*)tmp;
    cudaGetSymbolAddress(&tmp, g_Hh);    pHh   = (half*)tmp;
    cudaGetSymbolAddress(&tmp, g_Hl);    pHl   = (half*)tmp;
    cudaGetSymbolAddress(&tmp, g_W5uh);  pW5uh = (half*)tmp;
    cudaGetSymbolAddress(&tmp, g_W5ul);  pW5ul = (half*)tmp;
    cudaGetSymbolAddress(&tmp, g_Woh);   pWoh  = (half*)tmp;
    cudaGetSymbolAddress(&tmp, g_Wol);   pWol  = (half*)tmp;
    cudaGetSymbolAddress(&tmp, g_Ih);    pIh   = (half*)tmp;
    cudaGetSymbolAddress(&tmp, g_Il);    pIl   = (half*)tmp;

    const int GEMM_SMEM = 2 * 2 * (GBM + GBN) * SROW * (int)sizeof(half);
    cudaFuncSetAttribute(gemm3, cudaFuncAttributeMaxDynamicSharedMemorySize, GEMM_SMEM);

    const int PW_BLOCKS = (int)(((size_t)NCROW * HDIM) / 256);
    const int CH_BLOCKS = CH / 256;

    build_wcat<<<(KX * KX + 255) / 256, 256>>>(w3w, w3u, w4w, w4u, w5w);
    split_f32<<<(HDIM * HDIM + 255) / 256, 256>>>(w5u, pW5uh, pW5ul, HDIM * HDIM);
    split_f32<<<(HDIM * 2 * HDIM + 255) / 256, 256>>>(wout, pWoh, pWol, HDIM * 2 * HDIM);
    split_f32<<<(N_OBJ * HDIM + 255) / 256, 256>>>(input, pIh, pIl, N_OBJ * HDIM);

    /* B2 = input @ Wo2^T  (input-cols 512..1023 of w_out) */
    gemm3<<<dim3(N_OBJ / GBM, HDIM / GBN), 256, GEMM_SMEM>>>(
        pIh, pIl, HDIM, pWoh + 512, pWol + 512, 2 * HDIM, pB2, HDIM, HDIM);

    init_hidden<<<PW_BLOCKS, 256>>>(input);

    for (int t = 0; t < 3; t++) {
        colsum_kernel<<<CH_BLOCKS, 256>>>();
        msprop_kernel<<<CH_BLOCKS, 256>>>(matrix);
        prop_kernel<<<dim3(HDIM / P_HT, (C_CLS + P_DT - 1) / P_DT, N_OBJ), 256>>>(matrix);
        /* Y = X @ Wcat^T : [38656,1536] x [1536,1536] */
        gemm3<<<dim3(NCROW / GBM, KX / GBN), 256, GEMM_SMEM>>>(
            pXh, pXl, KX, pWch, pWcl, KX, pY, KX, KX);
        pw_rv<<<PW_BLOCKS, 256>>>(b4w, b4u);
        /* U5 = (rv*h) @ W5u^T */
        gemm3<<<dim3(NCROW / GBM, HDIM / GBN), 256, GEMM_SMEM>>>(
            pRHh, pRHl, HDIM, pW5uh, pW5ul, HDIM, pU5, HDIM, HDIM);
        pw_update<<<PW_BLOCKS, 256>>>(b3w, b3u, b5w, b5u);
    }

    /* O1 = hidden @ Wo1^T  (input-cols 0..511 of w_out) */
    gemm3<<<dim3(NCROW / GBM, HDIM / GBN), 256, GEMM_SMEM>>>(
        pHh, pHl, HDIM, pWoh, pWol, 2 * HDIM, pO1, HDIM, HDIM);
    pw_relu<<<PW_BLOCKS, 256>>>(bout);

    cls_partial<<<dim3(N_OBJ / 32, C_CLS), 160>>>(wcls);
    cls_reduce<<<(N_OBJ * C_CLS + 255) / 256, 256>>>(bcls, out);
}

// round 10
// speedup vs baseline: 1.0020x; 1.0017x over previous
#include <cuda_runtime.h>
#include <cuda_fp16.h>
#include <math.h>

#define N_OBJ 256
#define C_CLS 151
#define HDIM  512
#define NCROW (N_OBJ * C_CLS)
#define KX    1536
#define CH    (C_CLS * HDIM)

#define LO_SCALE     256.0f
#define LO_INV_SCALE 0.00390625f

/* ------------------- scratch: device globals (no allocs) ------------------ */
__device__ float g_hidden[(size_t)NCROW * HDIM];
__device__ half  g_Xh[(size_t)NCROW * KX];
__device__ half  g_Xl[(size_t)NCROW * KX];
__device__ float g_Y[(size_t)NCROW * KX];
__device__ half  g_RHh[(size_t)NCROW * HDIM];
__device__ half  g_RHl[(size_t)NCROW * HDIM];
__device__ half  g_Hh[(size_t)NCROW * HDIM];
__device__ half  g_Hl[(size_t)NCROW * HDIM];
__device__ float g_U5[(size_t)NCROW * HDIM];
__device__ float g_O1[(size_t)NCROW * HDIM];
__device__ float g_S[CH];
__device__ float g_MS1[CH];
__device__ float g_MS2[CH];
__device__ half  g_Wch[(size_t)KX * KX];
__device__ half  g_Wcl[(size_t)KX * KX];
__device__ half  g_W5uh[HDIM * HDIM];
__device__ half  g_W5ul[HDIM * HDIM];
__device__ half  g_Woh[HDIM * 2 * HDIM];
__device__ half  g_Wol[HDIM * 2 * HDIM];
__device__ half  g_Ih[N_OBJ * HDIM];
__device__ half  g_Il[N_OBJ * HDIM];
__device__ float g_B2[N_OBJ * HDIM];
__device__ float g_Pcls[(size_t)C_CLS * N_OBJ * C_CLS];

/* ------------------------------ helpers ----------------------------------- */
__device__ __forceinline__ void split_store(float v, half* ph, half* pl)
{
    half hi = __float2half_rn(v);
    *ph = hi;
    *pl = __float2half_rn((v - __half2float(hi)) * LO_SCALE);
}

__device__ __forceinline__ unsigned smem_u32(const void* p)
{
    return (unsigned)__cvta_generic_to_shared(p);
}

__device__ __forceinline__ void ldsm4(unsigned* r, unsigned addr)
{
    asm volatile("ldmatrix.sync.aligned.m8n8.x4.shared.b16 {%0,%1,%2,%3},[%4];"
        : "=r"(r[0]), "=r"(r[1]), "=r"(r[2]), "=r"(r[3]) : "r"(addr));
}

__device__ __forceinline__ void mma16816(float* c, const unsigned* a, const unsigned* b)
{
    asm volatile("mma.sync.aligned.m16n8k16.row.col.f32.f16.f16.f32 "
        "{%0,%1,%2,%3},{%4,%5,%6,%7},{%8,%9},{%0,%1,%2,%3};"
        : "+f"(c[0]), "+f"(c[1]), "+f"(c[2]), "+f"(c[3])
        : "r"(a[0]), "r"(a[1]), "r"(a[2]), "r"(a[3]), "r"(b[0]), "r"(b[1]));
}

__device__ __forceinline__ void cp16(void* dst_smem, const void* src_gmem)
{
    unsigned s = smem_u32(dst_smem);
    asm volatile("cp.async.cg.shared.global [%0], [%1], 16;" :: "r"(s), "l"(src_gmem));
}

__device__ __forceinline__ void cp_commit()
{
    asm volatile("cp.async.commit_group;" ::: "memory");
}

__device__ __forceinline__ void cp_wait0()
{
    asm volatile("cp.async.wait_group 0;" ::: "memory");
}

/* ------------------------- weight concat + split -------------------------- */
__global__ void build_wcat(const float* __restrict__ w3w, const float* __restrict__ w3u,
                           const float* __restrict__ w4w, const float* __restrict__ w4u,
                           const float* __restrict__ w5w)
{
    int idx = blockIdx.x * blockDim.x + threadIdx.x;
    if (idx >= KX * KX) return;
    int o = idx / KX;
    int k = idx - o * KX;
    float v;
    if (o < 512) {
        v = (k < 1024) ? w3w[o * 1024 + k] : w3u[o * 512 + (k - 1024)];
    } else if (o < 1024) {
        int oo = o - 512;
        v = (k < 1024) ? w4w[oo * 1024 + k] : w4u[oo * 512 + (k - 1024)];
    } else {
        int oo = o - 1024;
        v = (k < 1024) ? w5w[oo * 1024 + k] : 0.0f;
    }
    split_store(v, &g_Wch[idx], &g_Wcl[idx]);
}

__global__ void split_f32(const float* __restrict__ src, half* __restrict__ dh,
                          half* __restrict__ dl, int n)
{
    int idx = blockIdx.x * blockDim.x + threadIdx.x;
    if (idx >= n) return;
    split_store(src[idx], &dh[idx], &dl[idx]);
}

/* ------------------- init hidden[n][c][h] = input[n][h] ------------------- */
__global__ void init_hidden(const float* __restrict__ input)
{
    size_t idx = (size_t)blockIdx.x * blockDim.x + threadIdx.x;
    int h = (int)(idx & (HDIM - 1));
    size_t m = idx >> 9;
    int n = (int)(m / C_CLS);
    g_hidden[idx] = input[(size_t)n * HDIM + h];
}

/* -------------------- S[c][h] = sum_n hidden[n][c][h] --------------------- */
__global__ void colsum_kernel()
{
    int idx = blockIdx.x * blockDim.x + threadIdx.x;
    float s = 0.f;
    #pragma unroll 4
    for (int n = 0; n < N_OBJ; n++) s += g_hidden[(size_t)n * CH + idx];
    g_S[idx] = s;
}

/* --------- MS1[d][h]=sum_c M[c][d]S[c][h] ; MS2[d][h]=sum_c M[d][c]S ------ */
__global__ void msprop_kernel(const float* __restrict__ M)
{
    int idx = blockIdx.x * blockDim.x + threadIdx.x;
    int d = idx / HDIM;
    int h = idx - d * HDIM;
    float s1 = 0.f, s2 = 0.f;
    for (int c = 0; c < C_CLS; c++) {
        float sv = g_S[c * HDIM + h];
        s1 += M[c * C_CLS + d] * sv;
        s2 += M[d * C_CLS + c] * sv;
    }
    g_MS1[idx] = s1;
    g_MS2[idx] = s2;
}

/* ------ prop + X build: X[(n,d)] = [MS1-M^T h | MS2-M h | hidden] (split) -- */
#define P_DT 32
#define P_HT 64
__global__ __launch_bounds__(256) void prop_kernel(const float* __restrict__ M)
{
    __shared__ float Hs[8][P_HT];
    __shared__ float M1s[8][P_DT];
    __shared__ float M2s[8][P_DT];
    int n  = blockIdx.z;
    int d0 = blockIdx.y * P_DT;
    int h0 = blockIdx.x * P_HT;
    int tid = threadIdx.x;
    int hx = tid & 31;
    int ty = tid >> 5;
    float a1[4][2] = {{0.f, 0.f}, {0.f, 0.f}, {0.f, 0.f}, {0.f, 0.f}};
    float a2[4][2] = {{0.f, 0.f}, {0.f, 0.f}, {0.f, 0.f}, {0.f, 0.f}};
    const float* Hn = g_hidden + (size_t)n * CH;

    for (int c0 = 0; c0 < C_CLS; c0 += 8) {
        #pragma unroll
        for (int l = 0; l < 2; l++) {
            int f = tid + l * 256;
            int cc = f >> 6;
            int hh = f & 63;
            int c = c0 + cc;
            Hs[cc][hh] = (c < C_CLS) ? Hn[(size_t)c * HDIM + h0 + hh] : 0.f;
        }
        {
            int cc = tid >> 5;
            int dd = tid & 31;
            int c = c0 + cc;
            int d = d0 + dd;
            bool ok = (c < C_CLS) && (d < C_CLS);
            M1s[cc][dd] = ok ? M[c * C_CLS + d] : 0.f;
            M2s[cc][dd] = ok ? M[d * C_CLS + c] : 0.f;
        }
        __syncthreads();
        #pragma unroll
        for (int cc = 0; cc < 8; cc++) {
            float hv0 = Hs[cc][hx];
            float hv1 = Hs[cc][hx + 32];
            #pragma unroll
            for (int i = 0; i < 4; i++) {
                float m1 = M1s[cc][ty * 4 + i];
                float m2 = M2s[cc][ty * 4 + i];
                a1[i][0] += m1 * hv0;
                a1[i][1] += m1 * hv1;
                a2[i][0] += m2 * hv0;
                a2[i][1] += m2 * hv1;
            }
        }
        __syncthreads();
    }
    #pragma unroll
    for (int i = 0; i < 4; i++) {
        int d = d0 + ty * 4 + i;
        if (d < C_CLS) {
            size_t r = (size_t)(n * C_CLS + d) * KX;
            #pragma unroll
            for (int q = 0; q < 2; q++) {
                int h = h0 + hx + q * 32;
                float v1 = g_MS1[(size_t)d * HDIM + h] - a1[i][q];
                float v2 = g_MS2[(size_t)d * HDIM + h] - a2[i][q];
                float hv = Hn[(size_t)d * HDIM + h];
                split_store(v1, &g_Xh[r + h],        &g_Xl[r + h]);
                split_store(v2, &g_Xh[r + 512 + h],  &g_Xl[r + 512 + h]);
                split_store(hv, &g_Xh[r + 1024 + h], &g_Xl[r + 1024 + h]);
            }
        }
    }
}

/* ----------- tensor-core GEMM  C[m][n] = sum_k A[m][k] * B[n][k] ----------- */
/* fp32 via fp16 3-product split with scaled-lo residues and per-K-chunk      */
/* drain of the hi*hi MMA accumulator into a SEPARATE rn-add register sum.    */
/* C = accS + acl / LO_SCALE.                                                 */
/* Grid mapping: n-tile = blockIdx.x (FAST), m-tile = blockIdx.y (SLOW) so    */
/* concurrently-resident CTAs share B (L2-resident) and each A m-strip is     */
/* streamed from DRAM ~once instead of once per n-tile.                       */
#define GBM 128
#define GBN 128
#define GBK 32
#define SROW 40
#define SA_IDX(b, hl, r, c) (((((b) * 2 + (hl)) * GBM) + (r)) * SROW + (c))
#define SB_IDX(b, hl, r, c) (((((b) * 2 + (hl)) * GBN) + (r)) * SROW + (c))

__device__ __forceinline__ void gemm_load_stage(
    half* sA, half* sB, int s, int k0, int tid, int m0, int n0,
    const half* Ah, const half* Al, int lda,
    const half* Bh, const half* Bl, int ldb)
{
    #pragma unroll
    for (int t = 0; t < 2; t++) {
        int idx = tid + t * 256;
        int row = idx >> 2;
        int ck  = (idx & 3) * 8;
        cp16(&sA[SA_IDX(s, 0, row, ck)], Ah + (size_t)(m0 + row) * lda + k0 + ck);
        cp16(&sA[SA_IDX(s, 1, row, ck)], Al + (size_t)(m0 + row) * lda + k0 + ck);
        cp16(&sB[SB_IDX(s, 0, row, ck)], Bh + (size_t)(n0 + row) * ldb + k0 + ck);
        cp16(&sB[SB_IDX(s, 1, row, ck)], Bl + (size_t)(n0 + row) * ldb + k0 + ck);
    }
}

__global__ __launch_bounds__(256, 1) void gemm3(
    const half* __restrict__ Ah, const half* __restrict__ Al, int lda,
    const half* __restrict__ Bh, const half* __restrict__ Bl, int ldb,
    float* __restrict__ Cout, int ldc, int K)
{
    extern __shared__ half smem[];
    half* sA = smem;
    half* sB = smem + 2 * 2 * GBM * SROW;

    int tid = threadIdx.x;
    int warp = tid >> 5;
    int lane = tid & 31;
    int wm = warp >> 2;
    int wn = warp & 3;
    int m0 = blockIdx.y * GBM;   /* m slow */
    int n0 = blockIdx.x * GBN;   /* n fast */

    float acc[4][4][4];   /* hi*hi, drained each K-chunk */
    float accS[4][4][4];  /* rn drain target (never an MMA accumulator) */
    float acl[4][4][4];   /* hi*lo' + lo'*hi (scaled by LO_SCALE) */
    #pragma unroll
    for (int i = 0; i < 4; i++) {
        #pragma unroll
        for (int j = 0; j < 4; j++) {
            #pragma unroll
            for (int q = 0; q < 4; q++) {
                acc[i][j][q]  = 0.f;
                accS[i][j][q] = 0.f;
                acl[i][j][q]  = 0.f;
            }
        }
    }

    gemm_load_stage(sA, sB, 0, 0, tid, m0, n0, Ah, Al, lda, Bh, Bl, ldb);
    cp_commit();

    int nit = K / GBK;
    for (int it = 0; it < nit; it++) {
        int cur = it & 1;
        cp_wait0();
        __syncthreads();
        if (it + 1 < nit) {
            gemm_load_stage(sA, sB, cur ^ 1, (it + 1) * GBK, tid, m0, n0,
                            Ah, Al, lda, Bh, Bl, ldb);
            cp_commit();
        }
        #pragma unroll
        for (int ks = 0; ks < 2; ks++) {
            int kk = ks * 16;
            unsigned bhf[2][4];
            unsigned blf[2][4];
            #pragma unroll
            for (int p = 0; p < 2; p++) {
                int nn = wn * 32 + p * 16 + ((lane >> 4) << 3) + (lane & 7);
                int kb = kk + (((lane >> 3) & 1) << 3);
                ldsm4(bhf[p], smem_u32(&sB[SB_IDX(cur, 0, nn, kb)]));
                ldsm4(blf[p], smem_u32(&sB[SB_IDX(cur, 1, nn, kb)]));
            }
            #pragma unroll
            for (int mf = 0; mf < 4; mf++) {
                int mm = wm * 64 + mf * 16 + (lane & 15);
                int ka = kk + ((lane >> 4) << 3);
                unsigned ahf[4];
                unsigned alf[4];
                ldsm4(ahf, smem_u32(&sA[SA_IDX(cur, 0, mm, ka)]));
                ldsm4(alf, smem_u32(&sA[SA_IDX(cur, 1, mm, ka)]));
                /* pass 1: acc += ah*bh */
                #pragma unroll
                for (int nf = 0; nf < 4; nf++)
                    mma16816(acc[mf][nf], ahf, &bhf[nf >> 1][(nf & 1) * 2]);
                /* pass 2: acl += ah*bl' */
                #pragma unroll
                for (int nf = 0; nf < 4; nf++)
                    mma16816(acl[mf][nf], ahf, &blf[nf >> 1][(nf & 1) * 2]);
                /* pass 3: acl += al'*bh */
                #pragma unroll
                for (int nf = 0; nf < 4; nf++)
                    mma16816(acl[mf][nf], alf, &bhf[nf >> 1][(nf & 1) * 2]);
            }
        }
        /* drain hi*hi chunk into rn-add register sum; reset MMA accumulator */
        #pragma unroll
        for (int mf = 0; mf < 4; mf++) {
            #pragma unroll
            for (int nf = 0; nf < 4; nf++) {
                #pragma unroll
                for (int q = 0; q < 4; q++) {
                    accS[mf][nf][q] += acc[mf][nf][q];
                    acc[mf][nf][q] = 0.f;
                }
            }
        }
        __syncthreads();
    }

    int r = lane >> 2;
    int cb = (lane & 3) * 2;
    #pragma unroll
    for (int mf = 0; mf < 4; mf++) {
        #pragma unroll
        for (int nf = 0; nf < 4; nf++) {
            float* Cp = Cout + (size_t)(m0 + wm * 64 + mf * 16 + r) * ldc
                             + (n0 + wn * 32 + nf * 8 + cb);
            Cp[0] = accS[mf][nf][0] + acl[mf][nf][0] * LO_INV_SCALE;
            Cp[1] = accS[mf][nf][1] + acl[mf][nf][1] * LO_INV_SCALE;
            Cp += (size_t)8 * ldc;
            Cp[0] = accS[mf][nf][2] + acl[mf][nf][2] * LO_INV_SCALE;
            Cp[1] = accS[mf][nf][3] + acl[mf][nf][3] * LO_INV_SCALE;
        }
    }
}

/* ------------------------------ pointwise --------------------------------- */
__device__ __forceinline__ float sigmoidf_(float x)
{
    return 1.f / (1.f + expf(-x));
}

__global__ void pw_rv(const float* __restrict__ b4w, const float* __restrict__ b4u)
{
    size_t idx = (size_t)blockIdx.x * blockDim.x + threadIdx.x;
    int h = (int)(idx & (HDIM - 1));
    size_t m = idx >> 9;
    float r = g_Y[m * KX + 512 + h] + b4w[h] + b4u[h];
    float rh = sigmoidf_(r) * g_hidden[idx];
    split_store(rh, &g_RHh[idx], &g_RHl[idx]);
}

__global__ void pw_update(const float* __restrict__ b3w, const float* __restrict__ b3u,
                          const float* __restrict__ b5w, const float* __restrict__ b5u)
{
    size_t idx = (size_t)blockIdx.x * blockDim.x + threadIdx.x;
    int h = (int)(idx & (HDIM - 1));
    size_t m = idx >> 9;
    float z  = sigmoidf_(g_Y[m * KX + h] + b3w[h] + b3u[h]);
    float hv = tanhf(g_Y[m * KX + 1024 + h] + b5w[h] + g_U5[idx] + b5u[h]);
    float hp = g_hidden[idx];
    float nh = (1.f - z) * hp + z * hv;
    g_hidden[idx] = nh;
    split_store(nh, &g_Hh[idx], &g_Hl[idx]);
}

__global__ void pw_relu(const float* __restrict__ bout)
{
    size_t idx = (size_t)blockIdx.x * blockDim.x + threadIdx.x;
    int h = (int)(idx & (HDIM - 1));
    size_t m = idx >> 9;
    int n = (int)(m / C_CLS);
    float v = g_O1[idx] + g_B2[n * HDIM + h] + bout[h];
    g_O1[idx] = v > 0.f ? v : 0.f;
}

/* --------------------- classifier: split-K over c ------------------------- */
__global__ __launch_bounds__(160) void cls_partial(const float* __restrict__ wcls)
{
    __shared__ float O1s[32][64];
    int nt = blockIdx.x;
    int ks = blockIdx.y;
    int j = threadIdx.x;
    float acc[32];
    #pragma unroll
    for (int nn = 0; nn < 32; nn++) acc[nn] = 0.f;

    for (int kb = 0; kb < 512; kb += 64) {
        for (int f = threadIdx.x; f < 32 * 64; f += 160) {
            int nn = f >> 6;
            int kk = f & 63;
            O1s[nn][kk] = g_O1[(size_t)(nt * 32 + nn) * CH + ks * 512 + kb + kk];
        }
        __syncthreads();
        if (j < C_CLS) {
            const float* wrow = wcls + (size_t)j * CH + ks * 512 + kb;
            #pragma unroll 4
            for (int kk = 0; kk < 64; kk += 4) {
                float4 w = *(const float4*)(wrow + kk);
                #pragma unroll
                for (int nn = 0; nn < 32; nn++) {
                    float4 o = *(const float4*)&O1s[nn][kk];
                    acc[nn] += w.x * o.x + w.y * o.y + w.z * o.z + w.w * o.w;
                }
            }
        }
        __syncthreads();
    }
    if (j < C_CLS) {
        #pragma unroll
        for (int nn = 0; nn < 32; nn++)
            g_Pcls[((size_t)ks * N_OBJ + nt * 32 + nn) * C_CLS + j] = acc[nn];
    }
}

__global__ void cls_reduce(const float* __restrict__ bcls, float* __restrict__ out)
{
    int idx = blockIdx.x * blockDim.x + threadIdx.x;
    if (idx >= N_OBJ * C_CLS) return;
    int n = idx / C_CLS;
    int j = idx - n * C_CLS;
    float s = bcls[j];
    for (int ks = 0; ks < C_CLS; ks++)
        s += g_Pcls[((size_t)ks * N_OBJ + n) * C_CLS + j];
    out[idx] = s;
}

/* --------------------------------------------------------------------------- */
extern "C" void kernel_launch(void* const* d_in, const int* in_sizes, int n_in,
                              void* d_out, int out_size)
{
    const float* input  = (const float*)d_in[0];
    const float* matrix = (const float*)d_in[1];
    const float* w3w = (const float*)d_in[2];
    const float* b3w = (const float*)d_in[3];
    const float* w3u = (const float*)d_in[4];
    const float* b3u = (const float*)d_in[5];
    const float* w4w = (const float*)d_in[6];
    const float* b4w = (const float*)d_in[7];
    const float* w4u = (const float*)d_in[8];
    const float* b4u = (const float*)d_in[9];
    const float* w5w = (const float*)d_in[10];
    const float* b5w = (const float*)d_in[11];
    const float* w5u = (const float*)d_in[12];
    const float* b5u = (const float*)d_in[13];
    const float* wout = (const float*)d_in[14];
    const float* bout = (const float*)d_in[15];
    const float* wcls = (const float*)d_in[16];
    const float* bcls = (const float*)d_in[17];
    float* out = (float*)d_out;

    void* tmp = 0;
    float* pY;
    float* pU5;
    float* pO1;
    float* pB2;
    half* pXh;
    half* pXl;
    half* pWch;
    half* pWcl;
    half* pRHh;
    half* pRHl;
    half* pHh;
    half* pHl;
    half* pW5uh;
    half* pW5ul;
    half* pWoh;
    half* pWol;
    half* pIh;
    half* pIl;

    cudaGetSymbolAddress(&tmp, g_Y);     pY    = (float*)tmp;
    cudaGetSymbolAddress(&tmp, g_U5);    pU5   = (float*)tmp;
    cudaGetSymbolAddress(&tmp, g_O1);    pO1   = (float*)tmp;
    cudaGetSymbolAddress(&tmp, g_B2);    pB2   = (float*)tmp;
    cudaGetSymbolAddress(&tmp, g_Xh);    pXh   = (half*)tmp;
    cudaGetSymbolAddress(&tmp, g_Xl);    pXl   = (half*)tmp;
    cudaGetSymbolAddress(&tmp, g_Wch);   pWch  = (half*)tmp;
    cudaGetSymbolAddress(&tmp, g_Wcl);   pWcl  = (half*)tmp;
    cudaGetSymbolAddress(&tmp, g_RHh);   pRHh  = (half*)tmp;
    cudaGetSymbolAddress(&tmp, g_RHl);   pRHl  = (half*)tmp;
    cudaGetSymbolAddress(&tmp, g_Hh);    pHh   = (half*)tmp;
    cudaGetSymbolAddress(&tmp, g_Hl);    pHl   = (half*)tmp;
    cudaGetSymbolAddress(&tmp, g_W5uh);  pW5uh = (half*)tmp;
    cudaGetSymbolAddress(&tmp, g_W5ul);  pW5ul = (half*)tmp;
    cudaGetSymbolAddress(&tmp, g_Woh);   pWoh  = (half*)tmp;
    cudaGetSymbolAddress(&tmp, g_Wol);   pWol  = (half*)tmp;
    cudaGetSymbolAddress(&tmp, g_Ih);    pIh   = (half*)tmp;
    cudaGetSymbolAddress(&tmp, g_Il);    pIl   = (half*)tmp;

    const int GEMM_SMEM = 2 * 2 * (GBM + GBN) * SROW * (int)sizeof(half);
    cudaFuncSetAttribute(gemm3, cudaFuncAttributeMaxDynamicSharedMemorySize, GEMM_SMEM);

    const int PW_BLOCKS = (int)(((size_t)NCROW * HDIM) / 256);
    const int CH_BLOCKS = CH / 256;

    /* Launch order arranged so the profiled launch (0-based #3) is gemm3. */
    build_wcat<<<(KX * KX + 255) / 256, 256>>>(w3w, w3u, w4w, w4u, w5w);          /* 0 */
    split_f32<<<(HDIM * 2 * HDIM + 255) / 256, 256>>>(wout, pWoh, pWol,
                                                      HDIM * 2 * HDIM);           /* 1 */
    split_f32<<<(N_OBJ * HDIM + 255) / 256, 256>>>(input, pIh, pIl,
                                                   N_OBJ * HDIM);                 /* 2 */
    /* B2 = input @ Wo2^T  (input-cols 512..1023 of w_out)                    3 */
    gemm3<<<dim3(HDIM / GBN, N_OBJ / GBM), 256, GEMM_SMEM>>>(
        pIh, pIl, HDIM, pWoh + 512, pWol + 512, 2 * HDIM, pB2, HDIM, HDIM);
    split_f32<<<(HDIM * HDIM + 255) / 256, 256>>>(w5u, pW5uh, pW5ul, HDIM * HDIM);
    init_hidden<<<PW_BLOCKS, 256>>>(input);

    for (int t = 0; t < 3; t++) {
        colsum_kernel<<<CH_BLOCKS, 256>>>();
        msprop_kernel<<<CH_BLOCKS, 256>>>(matrix);
        prop_kernel<<<dim3(HDIM / P_HT, (C_CLS + P_DT - 1) / P_DT, N_OBJ), 256>>>(matrix);
        /* Y = X @ Wcat^T : [38656,1536] x [1536,1536] */
        gemm3<<<dim3(KX / GBN, NCROW / GBM), 256, GEMM_SMEM>>>(
            pXh, pXl, KX, pWch, pWcl, KX, pY, KX, KX);
        pw_rv<<<PW_BLOCKS, 256>>>(b4w, b4u);
        /* U5 = (rv*h) @ W5u^T */
        gemm3<<<dim3(HDIM / GBN, NCROW / GBM), 256, GEMM_SMEM>>>(
            pRHh, pRHl, HDIM, pW5uh, pW5ul, HDIM, pU5, HDIM, HDIM);
        pw_update<<<PW_BLOCKS, 256>>>(b3w, b3u, b5w, b5u);
    }

    /* O1 = hidden @ Wo1^T  (input-cols 0..511 of w_out) */
    gemm3<<<dim3(HDIM / GBN, NCROW / GBM), 256, GEMM_SMEM>>>(
        pHh, pHl, HDIM, pWoh, pWol, 2 * HDIM, pO1, HDIM, HDIM);
    pw_relu<<<PW_BLOCKS, 256>>>(bout);

    cls_partial<<<dim3(N_OBJ / 32, C_CLS), 160>>>(wcls);
    cls_reduce<<<(N_OBJ * C_CLS + 255) / 256, 256>>>(bcls, out);
}

// round 11
// speedup vs baseline: 1.1068x; 1.1046x over previous
#include <cuda_runtime.h>
#include <cuda_fp16.h>
#include <math.h>

#define N_OBJ 256
#define C_CLS 151
#define HDIM  512
#define NCROW (N_OBJ * C_CLS)
#define KX    1536
#define CH    (C_CLS * HDIM)

#define LO_SCALE     256.0f
#define LO_INV_SCALE 0.00390625f

/* ------------------- scratch: device globals (no allocs) ------------------ */
__device__ float g_hidden[(size_t)NCROW * HDIM];
__device__ half  g_Xh[(size_t)NCROW * KX];
__device__ half  g_Xl[(size_t)NCROW * KX];
__device__ float g_Y[(size_t)NCROW * KX];
__device__ half  g_RHh[(size_t)NCROW * HDIM];
__device__ half  g_RHl[(size_t)NCROW * HDIM];
__device__ half  g_Hh[(size_t)NCROW * HDIM];
__device__ half  g_Hl[(size_t)NCROW * HDIM];
__device__ float g_U5[(size_t)NCROW * HDIM];
__device__ float g_O1[(size_t)NCROW * HDIM];
__device__ float g_S[CH];
__device__ float g_MS1[CH];
__device__ float g_MS2[CH];
__device__ half  g_Wch[(size_t)KX * KX];
__device__ half  g_Wcl[(size_t)KX * KX];
__device__ half  g_W5uh[HDIM * HDIM];
__device__ half  g_W5ul[HDIM * HDIM];
__device__ half  g_Woh[HDIM * 2 * HDIM];
__device__ half  g_Wol[HDIM * 2 * HDIM];
__device__ half  g_Ih[N_OBJ * HDIM];
__device__ half  g_Il[N_OBJ * HDIM];
__device__ float g_B2[N_OBJ * HDIM];
__device__ float g_Pcls[(size_t)C_CLS * N_OBJ * C_CLS];

/* ------------------------------ helpers ----------------------------------- */
__device__ __forceinline__ void split_store(float v, half* ph, half* pl)
{
    half hi = __float2half_rn(v);
    *ph = hi;
    *pl = __float2half_rn((v - __half2float(hi)) * LO_SCALE);
}

__device__ __forceinline__ unsigned smem_u32(const void* p)
{
    return (unsigned)__cvta_generic_to_shared(p);
}

__device__ __forceinline__ void ldsm4(unsigned* r, unsigned addr)
{
    asm volatile("ldmatrix.sync.aligned.m8n8.x4.shared.b16 {%0,%1,%2,%3},[%4];"
        : "=r"(r[0]), "=r"(r[1]), "=r"(r[2]), "=r"(r[3]) : "r"(addr));
}

__device__ __forceinline__ void mma16816(float* c, const unsigned* a, const unsigned* b)
{
    asm volatile("mma.sync.aligned.m16n8k16.row.col.f32.f16.f16.f32 "
        "{%0,%1,%2,%3},{%4,%5,%6,%7},{%8,%9},{%0,%1,%2,%3};"
        : "+f"(c[0]), "+f"(c[1]), "+f"(c[2]), "+f"(c[3])
        : "r"(a[0]), "r"(a[1]), "r"(a[2]), "r"(a[3]), "r"(b[0]), "r"(b[1]));
}

__device__ __forceinline__ void cp16(void* dst_smem, const void* src_gmem)
{
    unsigned s = smem_u32(dst_smem);
    asm volatile("cp.async.cg.shared.global [%0], [%1], 16;" :: "r"(s), "l"(src_gmem));
}

__device__ __forceinline__ void cp_commit()
{
    asm volatile("cp.async.commit_group;" ::: "memory");
}

__device__ __forceinline__ void cp_wait0()
{
    asm volatile("cp.async.wait_group 0;" ::: "memory");
}

/* ------------------------- weight concat + split -------------------------- */
__global__ void build_wcat(const float* __restrict__ w3w, const float* __restrict__ w3u,
                           const float* __restrict__ w4w, const float* __restrict__ w4u,
                           const float* __restrict__ w5w)
{
    int idx = blockIdx.x * blockDim.x + threadIdx.x;
    if (idx >= KX * KX) return;
    int o = idx / KX;
    int k = idx - o * KX;
    float v;
    if (o < 512) {
        v = (k < 1024) ? w3w[o * 1024 + k] : w3u[o * 512 + (k - 1024)];
    } else if (o < 1024) {
        int oo = o - 512;
        v = (k < 1024) ? w4w[oo * 1024 + k] : w4u[oo * 512 + (k - 1024)];
    } else {
        int oo = o - 1024;
        v = (k < 1024) ? w5w[oo * 1024 + k] : 0.0f;
    }
    split_store(v, &g_Wch[idx], &g_Wcl[idx]);
}

__global__ void split_f32(const float* __restrict__ src, half* __restrict__ dh,
                          half* __restrict__ dl, int n)
{
    int idx = blockIdx.x * blockDim.x + threadIdx.x;
    if (idx >= n) return;
    split_store(src[idx], &dh[idx], &dl[idx]);
}

/* ------------------- init hidden[n][c][h] = input[n][h] ------------------- */
__global__ void init_hidden(const float* __restrict__ input)
{
    size_t idx = (size_t)blockIdx.x * blockDim.x + threadIdx.x;
    int h = (int)(idx & (HDIM - 1));
    size_t m = idx >> 9;
    int n = (int)(m / C_CLS);
    g_hidden[idx] = input[(size_t)n * HDIM + h];
}

/* -------------------- S[c][h] = sum_n hidden[n][c][h] --------------------- */
__global__ void colsum_kernel()
{
    int idx = blockIdx.x * blockDim.x + threadIdx.x;
    float s = 0.f;
    #pragma unroll 4
    for (int n = 0; n < N_OBJ; n++) s += g_hidden[(size_t)n * CH + idx];
    g_S[idx] = s;
}

/* --------- MS1[d][h]=sum_c M[c][d]S[c][h] ; MS2[d][h]=sum_c M[d][c]S ------ */
__global__ void msprop_kernel(const float* __restrict__ M)
{
    int idx = blockIdx.x * blockDim.x + threadIdx.x;
    int d = idx / HDIM;
    int h = idx - d * HDIM;
    float s1 = 0.f, s2 = 0.f;
    for (int c = 0; c < C_CLS; c++) {
        float sv = g_S[c * HDIM + h];
        s1 += M[c * C_CLS + d] * sv;
        s2 += M[d * C_CLS + c] * sv;
    }
    g_MS1[idx] = s1;
    g_MS2[idx] = s2;
}

/* ------ prop + X build: X[(n,d)] = [MS1-M^T h | MS2-M h | hidden] (split) -- */
#define P_DT 32
#define P_HT 64
__global__ __launch_bounds__(256) void prop_kernel(const float* __restrict__ M)
{
    __shared__ float Hs[8][P_HT];
    __shared__ float M1s[8][P_DT];
    __shared__ float M2s[8][P_DT];
    int n  = blockIdx.z;
    int d0 = blockIdx.y * P_DT;
    int h0 = blockIdx.x * P_HT;
    int tid = threadIdx.x;
    int hx = tid & 31;
    int ty = tid >> 5;
    float a1[4][2] = {{0.f, 0.f}, {0.f, 0.f}, {0.f, 0.f}, {0.f, 0.f}};
    float a2[4][2] = {{0.f, 0.f}, {0.f, 0.f}, {0.f, 0.f}, {0.f, 0.f}};
    const float* Hn = g_hidden + (size_t)n * CH;

    for (int c0 = 0; c0 < C_CLS; c0 += 8) {
        #pragma unroll
        for (int l = 0; l < 2; l++) {
            int f = tid + l * 256;
            int cc = f >> 6;
            int hh = f & 63;
            int c = c0 + cc;
            Hs[cc][hh] = (c < C_CLS) ? Hn[(size_t)c * HDIM + h0 + hh] : 0.f;
        }
        {
            int cc = tid >> 5;
            int dd = tid & 31;
            int c = c0 + cc;
            int d = d0 + dd;
            bool ok = (c < C_CLS) && (d < C_CLS);
            M1s[cc][dd] = ok ? M[c * C_CLS + d] : 0.f;
            M2s[cc][dd] = ok ? M[d * C_CLS + c] : 0.f;
        }
        __syncthreads();
        #pragma unroll
        for (int cc = 0; cc < 8; cc++) {
            float hv0 = Hs[cc][hx];
            float hv1 = Hs[cc][hx + 32];
            #pragma unroll
            for (int i = 0; i < 4; i++) {
                float m1 = M1s[cc][ty * 4 + i];
                float m2 = M2s[cc][ty * 4 + i];
                a1[i][0] += m1 * hv0;
                a1[i][1] += m1 * hv1;
                a2[i][0] += m2 * hv0;
                a2[i][1] += m2 * hv1;
            }
        }
        __syncthreads();
    }
    #pragma unroll
    for (int i = 0; i < 4; i++) {
        int d = d0 + ty * 4 + i;
        if (d < C_CLS) {
            size_t r = (size_t)(n * C_CLS + d) * KX;
            #pragma unroll
            for (int q = 0; q < 2; q++) {
                int h = h0 + hx + q * 32;
                float v1 = g_MS1[(size_t)d * HDIM + h] - a1[i][q];
                float v2 = g_MS2[(size_t)d * HDIM + h] - a2[i][q];
                float hv = Hn[(size_t)d * HDIM + h];
                split_store(v1, &g_Xh[r + h],        &g_Xl[r + h]);
                split_store(v2, &g_Xh[r + 512 + h],  &g_Xl[r + 512 + h]);
                split_store(hv, &g_Xh[r + 1024 + h], &g_Xl[r + 1024 + h]);
            }
        }
    }
}

/* ----------- tensor-core GEMM  C[m][n] = sum_k A[m][k] * B[n][k] ----------- */
/* fp32 via fp16 split with scaled-lo residues; corrections applied only for  */
/* k < KC (selective precision: large-magnitude K-segments get 3 products,    */
/* small-magnitude segments run hi-only). Per-K-chunk drain of the hi*hi MMA  */
/* accumulator into a separate rn-add register sum kills RZ-accumulate bias.  */
/* C = accS + acl / LO_SCALE.                                                 */
#define GBM 128
#define GBN 128
#define GBK 32
#define SROW 40
#define SA_IDX(b, hl, r, c) (((((b) * 2 + (hl)) * GBM) + (r)) * SROW + (c))
#define SB_IDX(b, hl, r, c) (((((b) * 2 + (hl)) * GBN) + (r)) * SROW + (c))

__device__ __forceinline__ void gemm_load_stage(
    half* sA, half* sB, int s, int k0, int tid, int m0, int n0,
    const half* Ah, const half* Al, int lda,
    const half* Bh, const half* Bl, int ldb, bool corr)
{
    #pragma unroll
    for (int t = 0; t < 2; t++) {
        int idx = tid + t * 256;
        int row = idx >> 2;
        int ck  = (idx & 3) * 8;
        cp16(&sA[SA_IDX(s, 0, row, ck)], Ah + (size_t)(m0 + row) * lda + k0 + ck);
        cp16(&sB[SB_IDX(s, 0, row, ck)], Bh + (size_t)(n0 + row) * ldb + k0 + ck);
        if (corr) {
            cp16(&sA[SA_IDX(s, 1, row, ck)], Al + (size_t)(m0 + row) * lda + k0 + ck);
            cp16(&sB[SB_IDX(s, 1, row, ck)], Bl + (size_t)(n0 + row) * ldb + k0 + ck);
        }
    }
}

__global__ __launch_bounds__(256, 1) void gemm3(
    const half* __restrict__ Ah, const half* __restrict__ Al, int lda,
    const half* __restrict__ Bh, const half* __restrict__ Bl, int ldb,
    float* __restrict__ Cout, int ldc, int K, int KC)
{
    extern __shared__ half smem[];
    half* sA = smem;
    half* sB = smem + 2 * 2 * GBM * SROW;

    int tid = threadIdx.x;
    int warp = tid >> 5;
    int lane = tid & 31;
    int wm = warp >> 2;
    int wn = warp & 3;
    int m0 = blockIdx.y * GBM;   /* m slow */
    int n0 = blockIdx.x * GBN;   /* n fast */

    float acc[4][4][4];   /* hi*hi, drained each K-chunk */
    float accS[4][4][4];  /* rn drain target (never an MMA accumulator) */
    float acl[4][4][4];   /* hi*lo' + lo'*hi (scaled by LO_SCALE) */
    #pragma unroll
    for (int i = 0; i < 4; i++) {
        #pragma unroll
        for (int j = 0; j < 4; j++) {
            #pragma unroll
            for (int q = 0; q < 4; q++) {
                acc[i][j][q]  = 0.f;
                accS[i][j][q] = 0.f;
                acl[i][j][q]  = 0.f;
            }
        }
    }

    gemm_load_stage(sA, sB, 0, 0, tid, m0, n0, Ah, Al, lda, Bh, Bl, ldb, 0 < KC);
    cp_commit();

    int nit = K / GBK;
    for (int it = 0; it < nit; it++) {
        int cur = it & 1;
        bool corr = (it * GBK) < KC;
        cp_wait0();
        __syncthreads();
        if (it + 1 < nit) {
            gemm_load_stage(sA, sB, cur ^ 1, (it + 1) * GBK, tid, m0, n0,
                            Ah, Al, lda, Bh, Bl, ldb, ((it + 1) * GBK) < KC);
            cp_commit();
        }
        #pragma unroll
        for (int ks = 0; ks < 2; ks++) {
            int kk = ks * 16;
            unsigned bhf[2][4];
            unsigned blf[2][4];
            #pragma unroll
            for (int p = 0; p < 2; p++) {
                int nn = wn * 32 + p * 16 + ((lane >> 4) << 3) + (lane & 7);
                int kb = kk + (((lane >> 3) & 1) << 3);
                ldsm4(bhf[p], smem_u32(&sB[SB_IDX(cur, 0, nn, kb)]));
                if (corr)
                    ldsm4(blf[p], smem_u32(&sB[SB_IDX(cur, 1, nn, kb)]));
            }
            #pragma unroll
            for (int mf = 0; mf < 4; mf++) {
                int mm = wm * 64 + mf * 16 + (lane & 15);
                int ka = kk + ((lane >> 4) << 3);
                unsigned ahf[4];
                unsigned alf[4];
                ldsm4(ahf, smem_u32(&sA[SA_IDX(cur, 0, mm, ka)]));
                if (corr)
                    ldsm4(alf, smem_u32(&sA[SA_IDX(cur, 1, mm, ka)]));
                /* pass 1: acc += ah*bh */
                #pragma unroll
                for (int nf = 0; nf < 4; nf++)
                    mma16816(acc[mf][nf], ahf, &bhf[nf >> 1][(nf & 1) * 2]);
                if (corr) {
                    /* pass 2: acl += ah*bl' */
                    #pragma unroll
                    for (int nf = 0; nf < 4; nf++)
                        mma16816(acl[mf][nf], ahf, &blf[nf >> 1][(nf & 1) * 2]);
                    /* pass 3: acl += al'*bh */
                    #pragma unroll
                    for (int nf = 0; nf < 4; nf++)
                        mma16816(acl[mf][nf], alf, &bhf[nf >> 1][(nf & 1) * 2]);
                }
            }
        }
        /* drain hi*hi chunk into rn-add register sum; reset MMA accumulator */
        #pragma unroll
        for (int mf = 0; mf < 4; mf++) {
            #pragma unroll
            for (int nf = 0; nf < 4; nf++) {
                #pragma unroll
                for (int q = 0; q < 4; q++) {
                    accS[mf][nf][q] += acc[mf][nf][q];
                    acc[mf][nf][q] = 0.f;
                }
            }
        }
        __syncthreads();
    }

    int r = lane >> 2;
    int cb = (lane & 3) * 2;
    #pragma unroll
    for (int mf = 0; mf < 4; mf++) {
        #pragma unroll
        for (int nf = 0; nf < 4; nf++) {
            float* Cp = Cout + (size_t)(m0 + wm * 64 + mf * 16 + r) * ldc
                             + (n0 + wn * 32 + nf * 8 + cb);
            Cp[0] = accS[mf][nf][0] + acl[mf][nf][0] * LO_INV_SCALE;
            Cp[1] = accS[mf][nf][1] + acl[mf][nf][1] * LO_INV_SCALE;
            Cp += (size_t)8 * ldc;
            Cp[0] = accS[mf][nf][2] + acl[mf][nf][2] * LO_INV_SCALE;
            Cp[1] = accS[mf][nf][3] + acl[mf][nf][3] * LO_INV_SCALE;
        }
    }
}

/* ------------------------------ pointwise --------------------------------- */
__device__ __forceinline__ float sigmoidf_(float x)
{
    return 1.f / (1.f + expf(-x));
}

__global__ void pw_rv(const float* __restrict__ b4w, const float* __restrict__ b4u)
{
    size_t idx = (size_t)blockIdx.x * blockDim.x + threadIdx.x;
    int h = (int)(idx & (HDIM - 1));
    size_t m = idx >> 9;
    float r = g_Y[m * KX + 512 + h] + b4w[h] + b4u[h];
    float rh = sigmoidf_(r) * g_hidden[idx];
    split_store(rh, &g_RHh[idx], &g_RHl[idx]);
}

__global__ void pw_update(const float* __restrict__ b3w, const float* __restrict__ b3u,
                          const float* __restrict__ b5w, const float* __restrict__ b5u)
{
    size_t idx = (size_t)blockIdx.x * blockDim.x + threadIdx.x;
    int h = (int)(idx & (HDIM - 1));
    size_t m = idx >> 9;
    float z  = sigmoidf_(g_Y[m * KX + h] + b3w[h] + b3u[h]);
    float hv = tanhf(g_Y[m * KX + 1024 + h] + b5w[h] + g_U5[idx] + b5u[h]);
    float hp = g_hidden[idx];
    float nh = (1.f - z) * hp + z * hv;
    g_hidden[idx] = nh;
    split_store(nh, &g_Hh[idx], &g_Hl[idx]);
}

__global__ void pw_relu(const float* __restrict__ bout)
{
    size_t idx = (size_t)blockIdx.x * blockDim.x + threadIdx.x;
    int h = (int)(idx & (HDIM - 1));
    size_t m = idx >> 9;
    int n = (int)(m / C_CLS);
    float v = g_O1[idx] + g_B2[n * HDIM + h] + bout[h];
    g_O1[idx] = v > 0.f ? v : 0.f;
}

/* --------------------- classifier: split-K over c ------------------------- */
__global__ __launch_bounds__(160) void cls_partial(const float* __restrict__ wcls)
{
    __shared__ float O1s[32][64];
    int nt = blockIdx.x;
    int ks = blockIdx.y;
    int j = threadIdx.x;
    float acc[32];
    #pragma unroll
    for (int nn = 0; nn < 32; nn++) acc[nn] = 0.f;

    for (int kb = 0; kb < 512; kb += 64) {
        for (int f = threadIdx.x; f < 32 * 64; f += 160) {
            int nn = f >> 6;
            int kk = f & 63;
            O1s[nn][kk] = g_O1[(size_t)(nt * 32 + nn) * CH + ks * 512 + kb + kk];
        }
        __syncthreads();
        if (j < C_CLS) {
            const float* wrow = wcls + (size_t)j * CH + ks * 512 + kb;
            #pragma unroll 4
            for (int kk = 0; kk < 64; kk += 4) {
                float4 w = *(const float4*)(wrow + kk);
                #pragma unroll
                for (int nn = 0; nn < 32; nn++) {
                    float4 o = *(const float4*)&O1s[nn][kk];
                    acc[nn] += w.x * o.x + w.y * o.y + w.z * o.z + w.w * o.w;
                }
            }
        }
        __syncthreads();
    }
    if (j < C_CLS) {
        #pragma unroll
        for (int nn = 0; nn < 32; nn++)
            g_Pcls[((size_t)ks * N_OBJ + nt * 32 + nn) * C_CLS + j] = acc[nn];
    }
}

__global__ void cls_reduce(const float* __restrict__ bcls, float* __restrict__ out)
{
    int idx = blockIdx.x * blockDim.x + threadIdx.x;
    if (idx >= N_OBJ * C_CLS) return;
    int n = idx / C_CLS;
    int j = idx - n * C_CLS;
    float s = bcls[j];
    for (int ks = 0; ks < C_CLS; ks++)
        s += g_Pcls[((size_t)ks * N_OBJ + n) * C_CLS + j];
    out[idx] = s;
}

/* --------------------------------------------------------------------------- */
extern "C" void kernel_launch(void* const* d_in, const int* in_sizes, int n_in,
                              void* d_out, int out_size)
{
    const float* input  = (const float*)d_in[0];
    const float* matrix = (const float*)d_in[1];
    const float* w3w = (const float*)d_in[2];
    const float* b3w = (const float*)d_in[3];
    const float* w3u = (const float*)d_in[4];
    const float* b3u = (const float*)d_in[5];
    const float* w4w = (const float*)d_in[6];
    const float* b4w = (const float*)d_in[7];
    const float* w4u = (const float*)d_in[8];
    const float* b4u = (const float*)d_in[9];
    const float* w5w = (const float*)d_in[10];
    const float* b5w = (const float*)d_in[11];
    const float* w5u = (const float*)d_in[12];
    const float* b5u = (const float*)d_in[13];
    const float* wout = (const float*)d_in[14];
    const float* bout = (const float*)d_in[15];
    const float* wcls = (const float*)d_in[16];
    const float* bcls = (const float*)d_in[17];
    float* out = (float*)d_out;

    void* tmp = 0;
    float* pY;
    float* pU5;
    float* pO1;
    float* pB2;
    half* pXh;
    half* pXl;
    half* pWch;
    half* pWcl;
    half* pRHh;
    half* pRHl;
    half* pHh;
    half* pHl;
    half* pW5uh;
    half* pW5ul;
    half* pWoh;
    half* pWol;
    half* pIh;
    half* pIl;

    cudaGetSymbolAddress(&tmp, g_Y);     pY    = (float*)tmp;
    cudaGetSymbolAddress(&tmp, g_U5);    pU5   = (float*)tmp;
    cudaGetSymbolAddress(&tmp, g_O1);    pO1   = (float*)tmp;
    cudaGetSymbolAddress(&tmp, g_B2);    pB2   = (float*)tmp;
    cudaGetSymbolAddress(&tmp, g_Xh);    pXh   = (half*)tmp;
    cudaGetSymbolAddress(&tmp, g_Xl);    pXl   = (half*)tmp;
    cudaGetSymbolAddress(&tmp, g_Wch);   pWch  = (half*)tmp;
    cudaGetSymbolAddress(&tmp, g_Wcl);   pWcl  = (half*)tmp;
    cudaGetSymbolAddress(&tmp, g_RHh);   pRHh  = (half*)tmp;
    cudaGetSymbolAddress(&tmp, g_RHl);   pRHl  = (half*)tmp;
    cudaGetSymbolAddress(&tmp, g_Hh);    pHh   = (half*)tmp;
    cudaGetSymbolAddress(&tmp, g_Hl);    pHl   = (half*)tmp;
    cudaGetSymbolAddress(&tmp, g_W5uh);  pW5uh = (half*)tmp;
    cudaGetSymbolAddress(&tmp, g_W5ul);  pW5ul = (half*)tmp;
    cudaGetSymbolAddress(&tmp, g_Woh);   pWoh  = (half*)tmp;
    cudaGetSymbolAddress(&tmp, g_Wol);   pWol  = (half*)tmp;
    cudaGetSymbolAddress(&tmp, g_Ih);    pIh   = (half*)tmp;
    cudaGetSymbolAddress(&tmp, g_Il);    pIl   = (half*)tmp;

    const int GEMM_SMEM = 2 * 2 * (GBM + GBN) * SROW * (int)sizeof(half);
    cudaFuncSetAttribute(gemm3, cudaFuncAttributeMaxDynamicSharedMemorySize, GEMM_SMEM);

    const int PW_BLOCKS = (int)(((size_t)NCROW * HDIM) / 256);
    const int CH_BLOCKS = CH / 256;

    build_wcat<<<(KX * KX + 255) / 256, 256>>>(w3w, w3u, w4w, w4u, w5w);
    split_f32<<<(HDIM * 2 * HDIM + 255) / 256, 256>>>(wout, pWoh, pWol,
                                                      HDIM * 2 * HDIM);
    split_f32<<<(N_OBJ * HDIM + 255) / 256, 256>>>(input, pIh, pIl,
                                                   N_OBJ * HDIM);
    /* B2 = input @ Wo2^T  (input-cols 512..1023 of w_out) — full corrections */
    gemm3<<<dim3(HDIM / GBN, N_OBJ / GBM), 256, GEMM_SMEM>>>(
        pIh, pIl, HDIM, pWoh + 512, pWol + 512, 2 * HDIM, pB2, HDIM, HDIM, HDIM);
    split_f32<<<(HDIM * HDIM + 255) / 256, 256>>>(w5u, pW5uh, pW5ul, HDIM * HDIM);
    init_hidden<<<PW_BLOCKS, 256>>>(input);

    for (int t = 0; t < 3; t++) {
        colsum_kernel<<<CH_BLOCKS, 256>>>();
        msprop_kernel<<<CH_BLOCKS, 256>>>(matrix);
        prop_kernel<<<dim3(HDIM / P_HT, (C_CLS + P_DT - 1) / P_DT, N_OBJ), 256>>>(matrix);
        /* Y = X @ Wcat^T : corrections only on av segments (k < 1024) */
        gemm3<<<dim3(KX / GBN, NCROW / GBM), 256, GEMM_SMEM>>>(
            pXh, pXl, KX, pWch, pWcl, KX, pY, KX, KX, 1024);
        pw_rv<<<PW_BLOCKS, 256>>>(b4w, b4u);
        /* U5 = (rv*h) @ W5u^T : small magnitudes — hi-only (KC=0) */
        gemm3<<<dim3(HDIM / GBN, NCROW / GBM), 256, GEMM_SMEM>>>(
            pRHh, pRHl, HDIM, pW5uh, pW5ul, HDIM, pU5, HDIM, HDIM, 0);
        pw_update<<<PW_BLOCKS, 256>>>(b3w, b3u, b5w, b5u);
    }

    /* O1 = hidden @ Wo1^T  (input-cols 0..511 of w_out) — full corrections */
    gemm3<<<dim3(HDIM / GBN, NCROW / GBM), 256, GEMM_SMEM>>>(
        pHh, pHl, HDIM, pWoh, pWol, 2 * HDIM, pO1, HDIM, HDIM, HDIM);
    pw_relu<<<PW_BLOCKS, 256>>>(bout);

    cls_partial<<<dim3(N_OBJ / 32, C_CLS), 160>>>(wcls);
    cls_reduce<<<(N_OBJ * C_CLS + 255) / 256, 256>>>(bcls, out);
}